// round 4
// baseline (speedup 1.0000x reference)
#include <cuda_runtime.h>
#include <cuda_bf16.h>
#include <math.h>
#include <cstdint>

// ---------------------------------------------------------------------------
// MiniBlock: x + attn(ln1(x)); then + mlp(ln2(.))
// B=4, T=2048, C=1024, H=16, D=64, FF=4096.
// GEMMs: mma.sync bf16 split (hi+lo, 3 products) with fp32 accumulation.
// Round 4: single-sync pipeline, early prefetch, ldsm/mma double buffering.
// ---------------------------------------------------------------------------

#define B_NUM 4
#define T_SEQ 2048
#define C_DIM 1024
#define H_NUM 16
#define D_HEAD 64
#define FF_DIM 4096
#define M_ROWS (B_NUM * T_SEQ)   // 8192

// ---------------- scratch (device globals; sanctioned no-alloc path) -------
__device__ float g_q [M_ROWS * C_DIM];
__device__ float g_k [M_ROWS * C_DIM];
__device__ float g_v [M_ROWS * C_DIM];
__device__ float g_at[M_ROWS * C_DIM];
__device__ float g_x2[M_ROWS * C_DIM];

__device__ __nv_bfloat16 g_ahi[M_ROWS * C_DIM];
__device__ __nv_bfloat16 g_alo[M_ROWS * C_DIM];
__device__ __nv_bfloat16 g_fhi[M_ROWS * FF_DIM];
__device__ __nv_bfloat16 g_flo[M_ROWS * FF_DIM];

__device__ __nv_bfloat16 g_wqh[C_DIM * C_DIM], g_wql[C_DIM * C_DIM];
__device__ __nv_bfloat16 g_wkh[C_DIM * C_DIM], g_wkl[C_DIM * C_DIM];
__device__ __nv_bfloat16 g_wvh[C_DIM * C_DIM], g_wvl[C_DIM * C_DIM];
__device__ __nv_bfloat16 g_woh[C_DIM * C_DIM], g_wol[C_DIM * C_DIM];
__device__ __nv_bfloat16 g_w1h[FF_DIM * C_DIM], g_w1l[FF_DIM * C_DIM];
__device__ __nv_bfloat16 g_w2h[C_DIM * FF_DIM], g_w2l[C_DIM * FF_DIM];

// ---------------- PTX helpers (sm_80-era only) ------------------------------
__device__ __forceinline__ uint32_t smem_u32(const void* p) {
    uint32_t a;
    asm("{ .reg .u64 t; cvta.to.shared.u64 t, %1; cvt.u32.u64 %0, t; }" : "=r"(a) : "l"(p));
    return a;
}
__device__ __forceinline__ void cp16(uint32_t dst, const void* src) {
    asm volatile("cp.async.cg.shared.global [%0], [%1], 16;" :: "r"(dst), "l"(src));
}
__device__ __forceinline__ void cp_commit() { asm volatile("cp.async.commit_group;" ::: "memory"); }
template <int N> __device__ __forceinline__ void cp_wait() {
    asm volatile("cp.async.wait_group %0;" :: "n"(N) : "memory");
}
__device__ __forceinline__ void ldsm4(uint32_t r[4], uint32_t addr) {
    asm volatile("ldmatrix.sync.aligned.m8n8.x4.shared.b16 {%0,%1,%2,%3}, [%4];"
                 : "=r"(r[0]), "=r"(r[1]), "=r"(r[2]), "=r"(r[3]) : "r"(addr));
}
__device__ __forceinline__ void mma_bf16(float c[4], const uint32_t a[4],
                                         uint32_t b0, uint32_t b1) {
    asm volatile(
        "mma.sync.aligned.m16n8k16.row.col.f32.bf16.bf16.f32 "
        "{%0,%1,%2,%3}, {%4,%5,%6,%7}, {%8,%9}, {%0,%1,%2,%3};"
        : "+f"(c[0]), "+f"(c[1]), "+f"(c[2]), "+f"(c[3])
        : "r"(a[0]), "r"(a[1]), "r"(a[2]), "r"(a[3]), "r"(b0), "r"(b1));
}

__device__ __forceinline__ void split1(float v, __nv_bfloat16& h, __nv_bfloat16& l) {
    h = __float2bfloat16(v);
    l = __float2bfloat16(v - __bfloat162float(h));
}

#define SWZ(x) ((x) ^ (((x) >> 3) & 0x70))

// ---------------------------------------------------------------------------
// Split-bf16 HMMA GEMM: C[M,N] = (Ahi+Alo)[M,K] @ (Bhi+Blo)^T  (B stored [N,K])
// Block tile 128x128x64, 256 threads (8 warps, 2x4), warp tile 64x32.
// Single-sync 3-buffer cp.async pipeline (2 chunks in flight), kstep
// register double-buffering, product-major mma ordering.
// ---------------------------------------------------------------------------
static constexpr int GEMM_STAGE = 65536;           // 4 x 16KB (Ahi,Alo,Bhi,Blo)
static constexpr int GEMM_SMEM  = 3 * GEMM_STAGE;  // 196608

template <int RELU, int SPLIT>
__global__ __launch_bounds__(256, 1)
void gemm_mma(const __nv_bfloat16* __restrict__ Ahi, const __nv_bfloat16* __restrict__ Alo,
              const __nv_bfloat16* __restrict__ Bhi, const __nv_bfloat16* __restrict__ Blo,
              const float* __restrict__ bias, const float* __restrict__ res,
              float* __restrict__ C, __nv_bfloat16* __restrict__ Ohi,
              __nv_bfloat16* __restrict__ Olo, int N, int K) {
    extern __shared__ __align__(1024) char smem[];
    const uint32_t sb = smem_u32(smem);
    const int tid = threadIdx.x;
    const int lane = tid & 31;
    const int wid = tid >> 5;
    const int warp_m = wid >> 2;   // 0..1
    const int warp_n = wid & 3;    // 0..3
    const int n0 = blockIdx.x * 128;
    const int m0 = blockIdx.y * 128;

    const int nc = K >> 6;   // 64-col chunks

    // ------ gmem load setup: thread owns row tid>>1, half (tid&1) of 128B ---
    const int lrow = tid >> 1;
    const int lhalf = (tid & 1) * 64;  // byte offset within row
    const char* pa0 = (const char*)(Ahi + (size_t)(m0 + lrow) * K) + lhalf;
    const char* pa1 = (const char*)(Alo + (size_t)(m0 + lrow) * K) + lhalf;
    const char* pb0 = (const char*)(Bhi + (size_t)(n0 + lrow) * K) + lhalf;
    const char* pb1 = (const char*)(Blo + (size_t)(n0 + lrow) * K) + lhalf;

    auto issue = [&](int c) {
        uint32_t base = sb + (uint32_t)(c % 3) * GEMM_STAGE;
        size_t koff = (size_t)(c << 6) * 2;  // bytes along K
#pragma unroll
        for (int j = 0; j < 4; j++) {
            uint32_t so = SWZ((uint32_t)(lrow * 128 + lhalf + j * 16));
            cp16(base + so,         pa0 + koff + j * 16);
            cp16(base + 16384 + so, pa1 + koff + j * 16);
            cp16(base + 32768 + so, pb0 + koff + j * 16);
            cp16(base + 49152 + so, pb1 + koff + j * 16);
        }
        cp_commit();
    };

    issue(0);
    if (nc > 1) issue(1);

    // ------ ldmatrix lane addressing ---------------------------------------
    const int rowA = (lane & 7) + ((lane >> 3) & 1) * 8;
    const int colA = (lane >> 4) * 16;
    const int rowB = (lane & 7) + (lane >> 4) * 8;
    const int colB = ((lane >> 3) & 1) * 16;

    float acc[4][4][4];
#pragma unroll
    for (int a = 0; a < 4; a++)
#pragma unroll
        for (int b = 0; b < 4; b++)
#pragma unroll
            for (int r = 0; r < 4; r++) acc[a][b][r] = 0.f;

    // double-buffered fragments across ksteps
    uint32_t ah[2][4][4], al[2][4][4], bh[2][2][4], bl[2][2][4];

    auto load_frag = [&](uint32_t stb, int ks, int buf) {
#pragma unroll
        for (int mt = 0; mt < 4; mt++) {
            uint32_t off = (uint32_t)((warp_m * 64 + mt * 16 + rowA) * 128 + ks * 32 + colA);
            uint32_t sw = SWZ(off);
            ldsm4(ah[buf][mt], stb + sw);
            ldsm4(al[buf][mt], stb + 16384 + sw);
        }
#pragma unroll
        for (int np = 0; np < 2; np++) {
            uint32_t off = (uint32_t)((warp_n * 32 + np * 16 + rowB) * 128 + ks * 32 + colB);
            uint32_t sw = SWZ(off);
            ldsm4(bh[buf][np], stb + 32768 + sw);
            ldsm4(bl[buf][np], stb + 49152 + sw);
        }
    };

    for (int c = 0; c < nc; c++) {
        if (c + 1 < nc) cp_wait<1>(); else cp_wait<0>();
        __syncthreads();                    // data visible; prev chunk fully consumed
        if (c + 2 < nc) issue(c + 2);       // buffer (c+2)%3 free (last read in chunk c-1)

        uint32_t stb = sb + (uint32_t)(c % 3) * GEMM_STAGE;
        load_frag(stb, 0, 0);
#pragma unroll
        for (int ks = 0; ks < 4; ks++) {
            const int cur = ks & 1;
            if (ks < 3) load_frag(stb, ks + 1, cur ^ 1);  // hide LDS behind mma
            // product-major: same accumulator touched 16 mmas apart
#pragma unroll
            for (int mt = 0; mt < 4; mt++)
#pragma unroll
                for (int nt = 0; nt < 4; nt++)
                    mma_bf16(acc[mt][nt], ah[cur][mt],
                             bh[cur][nt >> 1][(nt & 1) * 2], bh[cur][nt >> 1][(nt & 1) * 2 + 1]);
#pragma unroll
            for (int mt = 0; mt < 4; mt++)
#pragma unroll
                for (int nt = 0; nt < 4; nt++)
                    mma_bf16(acc[mt][nt], al[cur][mt],
                             bh[cur][nt >> 1][(nt & 1) * 2], bh[cur][nt >> 1][(nt & 1) * 2 + 1]);
#pragma unroll
            for (int mt = 0; mt < 4; mt++)
#pragma unroll
                for (int nt = 0; nt < 4; nt++)
                    mma_bf16(acc[mt][nt], ah[cur][mt],
                             bl[cur][nt >> 1][(nt & 1) * 2], bl[cur][nt >> 1][(nt & 1) * 2 + 1]);
        }
    }

    // ------ epilogue -------------------------------------------------------
    const int rbase = m0 + warp_m * 64 + (lane >> 2);
    const int cbase = n0 + warp_n * 32 + (lane & 3) * 2;
#pragma unroll
    for (int mt = 0; mt < 4; mt++) {
#pragma unroll
        for (int nt = 0; nt < 4; nt++) {
            int col = cbase + nt * 8;
#pragma unroll
            for (int half = 0; half < 2; half++) {
                int row = rbase + mt * 16 + half * 8;
                float v0 = acc[mt][nt][half * 2 + 0];
                float v1 = acc[mt][nt][half * 2 + 1];
                if (bias) {
                    float2 b2 = *(const float2*)(bias + col);
                    v0 += b2.x; v1 += b2.y;
                }
                if (res) {
                    float2 r2 = *(const float2*)(res + (size_t)row * N + col);
                    v0 += r2.x; v1 += r2.y;
                }
                if (RELU) { v0 = fmaxf(v0, 0.f); v1 = fmaxf(v1, 0.f); }
                if (SPLIT) {
                    __nv_bfloat16 h0, l0, h1, l1;
                    split1(v0, h0, l0);
                    split1(v1, h1, l1);
                    *(__nv_bfloat162*)(Ohi + (size_t)row * N + col) = __halves2bfloat162(h0, h1);
                    *(__nv_bfloat162*)(Olo + (size_t)row * N + col) = __halves2bfloat162(l0, l1);
                } else {
                    float2 o2; o2.x = v0; o2.y = v1;
                    *(float2*)(C + (size_t)row * N + col) = o2;
                }
            }
        }
    }
}

// ---------------------------------------------------------------------------
// LayerNorm -> bf16 hi/lo split output. One block per row, 256 threads.
// ---------------------------------------------------------------------------
__global__ void ln_split(const float* __restrict__ x, const float* __restrict__ g,
                         const float* __restrict__ b, __nv_bfloat16* __restrict__ hi,
                         __nv_bfloat16* __restrict__ lo) {
    int row = blockIdx.x;
    int tid = threadIdx.x;
    const float4* xr = (const float4*)(x + (size_t)row * C_DIM);
    float4 v = xr[tid];
    float s = v.x + v.y + v.z + v.w;
    float q = v.x * v.x + v.y * v.y + v.z * v.z + v.w * v.w;
#pragma unroll
    for (int o = 16; o > 0; o >>= 1) {
        s += __shfl_xor_sync(0xffffffffu, s, o);
        q += __shfl_xor_sync(0xffffffffu, q, o);
    }
    __shared__ float ss[8], qs[8];
    if ((tid & 31) == 0) { ss[tid >> 5] = s; qs[tid >> 5] = q; }
    __syncthreads();
    float ts = 0.f, tq = 0.f;
#pragma unroll
    for (int i = 0; i < 8; i++) { ts += ss[i]; tq += qs[i]; }
    float mu = ts * (1.0f / C_DIM);
    float var = tq * (1.0f / C_DIM) - mu * mu;
    float rstd = rsqrtf(var + 1e-5f);
    float4 gg = ((const float4*)g)[tid];
    float4 bb = ((const float4*)b)[tid];
    float o0 = (v.x - mu) * rstd * gg.x + bb.x;
    float o1 = (v.y - mu) * rstd * gg.y + bb.y;
    float o2 = (v.z - mu) * rstd * gg.z + bb.z;
    float o3 = (v.w - mu) * rstd * gg.w + bb.w;
    __nv_bfloat16 h0, l0, h1, l1, h2, l2, h3, l3;
    split1(o0, h0, l0); split1(o1, h1, l1); split1(o2, h2, l2); split1(o3, h3, l3);
    __nv_bfloat162* ph = (__nv_bfloat162*)(hi + (size_t)row * C_DIM);
    __nv_bfloat162* pl = (__nv_bfloat162*)(lo + (size_t)row * C_DIM);
    ph[tid * 2]     = __halves2bfloat162(h0, h1);
    ph[tid * 2 + 1] = __halves2bfloat162(h2, h3);
    pl[tid * 2]     = __halves2bfloat162(l0, l1);
    pl[tid * 2 + 1] = __halves2bfloat162(l2, l3);
}

// elementwise split: fp32 -> bf16 hi/lo
__global__ void split_plain(const float* __restrict__ x, __nv_bfloat16* __restrict__ hi,
                            __nv_bfloat16* __restrict__ lo) {
    size_t i = ((size_t)blockIdx.x * blockDim.x + threadIdx.x) * 4;
    float4 v = *(const float4*)(x + i);
    __nv_bfloat16 h0, l0, h1, l1, h2, l2, h3, l3;
    split1(v.x, h0, l0); split1(v.y, h1, l1); split1(v.z, h2, l2); split1(v.w, h3, l3);
    __nv_bfloat162* ph = (__nv_bfloat162*)(hi + i);
    __nv_bfloat162* pl = (__nv_bfloat162*)(lo + i);
    ph[0] = __halves2bfloat162(h0, h1);
    ph[1] = __halves2bfloat162(h2, h3);
    pl[0] = __halves2bfloat162(l0, l1);
    pl[1] = __halves2bfloat162(l2, l3);
}

// weight transpose+split: W[K,N] -> T[N,K] (hi/lo bf16)
__global__ void wsplit_t(const float* __restrict__ W, __nv_bfloat16* __restrict__ Thi,
                         __nv_bfloat16* __restrict__ Tlo, int K, int N) {
    __shared__ float t[32][33];
    int n0 = blockIdx.x * 32, k0 = blockIdx.y * 32;
    int tx = threadIdx.x, ty = threadIdx.y;  // 32x8
#pragma unroll
    for (int i = 0; i < 32; i += 8) t[ty + i][tx] = W[(size_t)(k0 + ty + i) * N + n0 + tx];
    __syncthreads();
#pragma unroll
    for (int i = 0; i < 32; i += 8) {
        float v = t[tx][ty + i];
        __nv_bfloat16 h, l;
        split1(v, h, l);
        size_t o = (size_t)(n0 + ty + i) * K + k0 + tx;
        Thi[o] = h;
        Tlo[o] = l;
    }
}

// ---------------------------------------------------------------------------
// Flash attention (fp32, causal) — unchanged.
// ---------------------------------------------------------------------------
struct AttnSmem {
    float Qs[64][65];
    float Kt[64][65];
    float Vs[64][64];
    float Ssh[64][65];
    float mbuf[64];
    float abuf[64];
    float lbuf[64];
};

__global__ __launch_bounds__(256, 2)
void attn_kernel(const float* __restrict__ Q, const float* __restrict__ K,
                 const float* __restrict__ V, float* __restrict__ Out) {
    extern __shared__ AttnSmem sm[];
    AttnSmem& s = sm[0];

    int qt = blockIdx.x, h = blockIdx.y, b = blockIdx.z;
    int tid = threadIdx.x;
    int tx = tid & 15, ty = tid >> 4;
    int q0 = qt * 64;

    int lrow = tid >> 2;
    int dbase = (tid & 3) * 16;

    size_t qoff = ((size_t)(b * T_SEQ + q0 + lrow)) * C_DIM + h * D_HEAD + dbase;
#pragma unroll
    for (int i = 0; i < 16; i += 4) {
        float4 t = *(const float4*)(Q + qoff + i);
        s.Qs[lrow][dbase + i + 0] = t.x; s.Qs[lrow][dbase + i + 1] = t.y;
        s.Qs[lrow][dbase + i + 2] = t.z; s.Qs[lrow][dbase + i + 3] = t.w;
    }
    if (tid < 64) { s.mbuf[tid] = -3e30f; s.lbuf[tid] = 0.f; }
    float O[4][4] = {};
    __syncthreads();

    for (int kt = 0; kt <= qt; kt++) {
        int k0 = kt * 64;
        size_t koff = ((size_t)(b * T_SEQ + k0 + lrow)) * C_DIM + h * D_HEAD + dbase;
#pragma unroll
        for (int i = 0; i < 16; i += 4) {
            float4 t = *(const float4*)(K + koff + i);
            s.Kt[dbase + i + 0][lrow] = t.x; s.Kt[dbase + i + 1][lrow] = t.y;
            s.Kt[dbase + i + 2][lrow] = t.z; s.Kt[dbase + i + 3][lrow] = t.w;
            float4 u = *(const float4*)(V + koff + i);
            *(float4*)&s.Vs[lrow][dbase + i] = u;
        }
        __syncthreads();

        float Sv[4][4] = {};
#pragma unroll 8
        for (int d = 0; d < 64; d++) {
            float qv[4], kv[4];
#pragma unroll
            for (int i = 0; i < 4; i++) qv[i] = s.Qs[ty * 4 + i][d];
#pragma unroll
            for (int j = 0; j < 4; j++) kv[j] = s.Kt[d][tx * 4 + j];
#pragma unroll
            for (int i = 0; i < 4; i++)
#pragma unroll
                for (int j = 0; j < 4; j++)
                    Sv[i][j] += qv[i] * kv[j];
        }
        const float scale = 0.125f;
        bool diag = (kt == qt);
#pragma unroll
        for (int i = 0; i < 4; i++)
#pragma unroll
            for (int j = 0; j < 4; j++) {
                float val = Sv[i][j] * scale;
                if (diag && (tx * 4 + j) > (ty * 4 + i)) val = -3e30f;
                Sv[i][j] = val;
                s.Ssh[ty * 4 + i][tx * 4 + j] = val;
            }
        __syncthreads();

        if (tid < 64) {
            float mo = s.mbuf[tid];
            float mn = mo;
#pragma unroll 8
            for (int c = 0; c < 64; c++) mn = fmaxf(mn, s.Ssh[tid][c]);
            s.abuf[tid] = __expf(mo - mn);
            s.mbuf[tid] = mn;
        }
        __syncthreads();

        float mn[4], al[4];
#pragma unroll
        for (int i = 0; i < 4; i++) { mn[i] = s.mbuf[ty * 4 + i]; al[i] = s.abuf[ty * 4 + i]; }
#pragma unroll
        for (int i = 0; i < 4; i++)
#pragma unroll
            for (int j = 0; j < 4; j++) {
                Sv[i][j] = __expf(Sv[i][j] - mn[i]);
                O[i][j] *= al[i];
            }
#pragma unroll
        for (int i = 0; i < 4; i++)
#pragma unroll
            for (int j = 0; j < 4; j++)
                s.Ssh[ty * 4 + i][tx * 4 + j] = Sv[i][j];
        __syncthreads();

        if (tid < 64) {
            float acc = 0.f;
#pragma unroll 8
            for (int c = 0; c < 64; c++) acc += s.Ssh[tid][c];
            s.lbuf[tid] = s.lbuf[tid] * s.abuf[tid] + acc;
        }

#pragma unroll 4
        for (int c = 0; c < 64; c++) {
            float pv[4];
#pragma unroll
            for (int i = 0; i < 4; i++) pv[i] = s.Ssh[ty * 4 + i][c];
            float4 vv = *(const float4*)&s.Vs[c][tx * 4];
#pragma unroll
            for (int i = 0; i < 4; i++) {
                O[i][0] += pv[i] * vv.x; O[i][1] += pv[i] * vv.y;
                O[i][2] += pv[i] * vv.z; O[i][3] += pv[i] * vv.w;
            }
        }
        __syncthreads();
    }

    float linv[4];
#pragma unroll
    for (int i = 0; i < 4; i++) linv[i] = 1.0f / s.lbuf[ty * 4 + i];
#pragma unroll
    for (int i = 0; i < 4; i++) {
        size_t row = (size_t)(b * T_SEQ + q0 + ty * 4 + i);
        float4 o4;
        o4.x = O[i][0] * linv[i]; o4.y = O[i][1] * linv[i];
        o4.z = O[i][2] * linv[i]; o4.w = O[i][3] * linv[i];
        *(float4*)(Out + row * C_DIM + h * D_HEAD + tx * 4) = o4;
    }
}

// ---------------------------------------------------------------------------
// Launch (ordered so ncu -s 5 -c 1 captures a GEMM as the 6th launch)
// ---------------------------------------------------------------------------
extern "C" void kernel_launch(void* const* d_in, const int* in_sizes, int n_in,
                              void* d_out, int out_size) {
    const float* x    = (const float*)d_in[0];
    const float* Wq   = (const float*)d_in[1];
    const float* Wk   = (const float*)d_in[2];
    const float* Wv   = (const float*)d_in[3];
    const float* Wo   = (const float*)d_in[4];
    const float* bo   = (const float*)d_in[5];
    const float* ln1g = (const float*)d_in[6];
    const float* ln1b = (const float*)d_in[7];
    const float* ln2g = (const float*)d_in[8];
    const float* ln2b = (const float*)d_in[9];
    const float* W1   = (const float*)d_in[10];
    const float* b1   = (const float*)d_in[11];
    const float* W2   = (const float*)d_in[12];
    const float* b2   = (const float*)d_in[13];
    float* out = (float*)d_out;

    float *q, *k, *v, *at, *x2;
    __nv_bfloat16 *ahi, *alo, *fhi, *flo;
    __nv_bfloat16 *wqh, *wql, *wkh, *wkl, *wvh, *wvl, *woh, *wol, *w1h, *w1l, *w2h, *w2l;
    cudaGetSymbolAddress((void**)&q,   g_q);
    cudaGetSymbolAddress((void**)&k,   g_k);
    cudaGetSymbolAddress((void**)&v,   g_v);
    cudaGetSymbolAddress((void**)&at,  g_at);
    cudaGetSymbolAddress((void**)&x2,  g_x2);
    cudaGetSymbolAddress((void**)&ahi, g_ahi);
    cudaGetSymbolAddress((void**)&alo, g_alo);
    cudaGetSymbolAddress((void**)&fhi, g_fhi);
    cudaGetSymbolAddress((void**)&flo, g_flo);
    cudaGetSymbolAddress((void**)&wqh, g_wqh); cudaGetSymbolAddress((void**)&wql, g_wql);
    cudaGetSymbolAddress((void**)&wkh, g_wkh); cudaGetSymbolAddress((void**)&wkl, g_wkl);
    cudaGetSymbolAddress((void**)&wvh, g_wvh); cudaGetSymbolAddress((void**)&wvl, g_wvl);
    cudaGetSymbolAddress((void**)&woh, g_woh); cudaGetSymbolAddress((void**)&wol, g_wol);
    cudaGetSymbolAddress((void**)&w1h, g_w1h); cudaGetSymbolAddress((void**)&w1l, g_w1l);
    cudaGetSymbolAddress((void**)&w2h, g_w2h); cudaGetSymbolAddress((void**)&w2l, g_w2l);

    cudaFuncSetAttribute(attn_kernel, cudaFuncAttributeMaxDynamicSharedMemorySize,
                         (int)sizeof(AttnSmem));
    cudaFuncSetAttribute(gemm_mma<0, 0>, cudaFuncAttributeMaxDynamicSharedMemorySize, GEMM_SMEM);
    cudaFuncSetAttribute(gemm_mma<1, 1>, cudaFuncAttributeMaxDynamicSharedMemorySize, GEMM_SMEM);

    dim3 wblk(32, 8);
    dim3 g1024(C_DIM / 128, M_ROWS / 128);
    dim3 g4096(FF_DIM / 128, M_ROWS / 128);

    // #1-#3: QKV weight transpose + split
    wsplit_t<<<dim3(C_DIM / 32, C_DIM / 32), wblk>>>(Wq, wqh, wql, C_DIM, C_DIM);
    wsplit_t<<<dim3(C_DIM / 32, C_DIM / 32), wblk>>>(Wk, wkh, wkl, C_DIM, C_DIM);
    wsplit_t<<<dim3(C_DIM / 32, C_DIM / 32), wblk>>>(Wv, wvh, wvl, C_DIM, C_DIM);
    // #4: ln1 -> split activations
    ln_split<<<M_ROWS, 256>>>(x, ln1g, ln1b, ahi, alo);
    // #5: Q projection
    gemm_mma<0, 0><<<g1024, 256, GEMM_SMEM>>>(ahi, alo, wqh, wql, nullptr, nullptr,
                                              q, nullptr, nullptr, C_DIM, C_DIM);
    // #6: K projection  <-- ncu -s 5 -c 1 captures this launch
    gemm_mma<0, 0><<<g1024, 256, GEMM_SMEM>>>(ahi, alo, wkh, wkl, nullptr, nullptr,
                                              k, nullptr, nullptr, C_DIM, C_DIM);
    // #7: V projection
    gemm_mma<0, 0><<<g1024, 256, GEMM_SMEM>>>(ahi, alo, wvh, wvl, nullptr, nullptr,
                                              v, nullptr, nullptr, C_DIM, C_DIM);
    // #8-#10: remaining weight splits
    wsplit_t<<<dim3(C_DIM / 32, C_DIM / 32), wblk>>>(Wo, woh, wol, C_DIM, C_DIM);
    wsplit_t<<<dim3(FF_DIM / 32, C_DIM / 32), wblk>>>(W1, w1h, w1l, C_DIM, FF_DIM);
    wsplit_t<<<dim3(C_DIM / 32, FF_DIM / 32), wblk>>>(W2, w2h, w2l, FF_DIM, C_DIM);
    // #11: causal flash attention
    attn_kernel<<<dim3(T_SEQ / 64, H_NUM, B_NUM), 256, sizeof(AttnSmem)>>>(q, k, v, at);
    // #12: split attention output
    split_plain<<<(M_ROWS * C_DIM) / (256 * 4), 256>>>(at, ahi, alo);
    // #13: Wo projection + bias + residual -> x2
    gemm_mma<0, 0><<<g1024, 256, GEMM_SMEM>>>(ahi, alo, woh, wol, bo, x,
                                              x2, nullptr, nullptr, C_DIM, C_DIM);
    // #14: ln2 -> split
    ln_split<<<M_ROWS, 256>>>(x2, ln2g, ln2b, ahi, alo);
    // #15: MLP up + ReLU (bf16-split output straight to ff buffers)
    gemm_mma<1, 1><<<g4096, 256, GEMM_SMEM>>>(ahi, alo, w1h, w1l, b1, nullptr,
                                              nullptr, fhi, flo, FF_DIM, C_DIM);
    // #16: MLP down + bias + residual -> out
    gemm_mma<0, 0><<<g1024, 256, GEMM_SMEM>>>(fhi, flo, w2h, w2l, b2, x2,
                                              out, nullptr, nullptr, C_DIM, FF_DIM);
}

// round 5
// speedup vs baseline: 2.0577x; 2.0577x over previous
#include <cuda_runtime.h>
#include <cuda_fp16.h>
#include <math.h>
#include <cstdint>

// ---------------------------------------------------------------------------
// MiniBlock: x + attn(ln1(x)); then + mlp(ln2(.))
// B=4, T=2048, C=1024, H=16, D=64, FF=4096.
// GEMMs: mma.sync fp16, weights split hi+lo (2 products), activations fp16.
// Attention: flash, fully on mma.sync fp16.
// ---------------------------------------------------------------------------

#define B_NUM 4
#define T_SEQ 2048
#define C_DIM 1024
#define H_NUM 16
#define D_HEAD 64
#define FF_DIM 4096
#define M_ROWS (B_NUM * T_SEQ)   // 8192

// ---------------- scratch (device globals) ----------------------------------
__device__ __half g_a  [M_ROWS * C_DIM];   // ln output (fp16 activations)
__device__ __half g_qh [M_ROWS * C_DIM];
__device__ __half g_kh [M_ROWS * C_DIM];
__device__ __half g_vh [M_ROWS * C_DIM];
__device__ __half g_at [M_ROWS * C_DIM];   // attention output
__device__ __half g_ffh[M_ROWS * FF_DIM];
__device__ float  g_x2 [M_ROWS * C_DIM];

__device__ __half g_wqh[C_DIM * C_DIM], g_wql[C_DIM * C_DIM];
__device__ __half g_wkh[C_DIM * C_DIM], g_wkl[C_DIM * C_DIM];
__device__ __half g_wvh[C_DIM * C_DIM], g_wvl[C_DIM * C_DIM];
__device__ __half g_woh[C_DIM * C_DIM], g_wol[C_DIM * C_DIM];
__device__ __half g_w1h[FF_DIM * C_DIM], g_w1l[FF_DIM * C_DIM];
__device__ __half g_w2h[C_DIM * FF_DIM], g_w2l[C_DIM * FF_DIM];

// ---------------- PTX helpers ------------------------------------------------
__device__ __forceinline__ uint32_t smem_u32(const void* p) {
    uint32_t a;
    asm("{ .reg .u64 t; cvta.to.shared.u64 t, %1; cvt.u32.u64 %0, t; }" : "=r"(a) : "l"(p));
    return a;
}
__device__ __forceinline__ void cp16(uint32_t dst, const void* src) {
    asm volatile("cp.async.cg.shared.global [%0], [%1], 16;" :: "r"(dst), "l"(src));
}
__device__ __forceinline__ void cp_commit() { asm volatile("cp.async.commit_group;" ::: "memory"); }
template <int N> __device__ __forceinline__ void cp_wait() {
    asm volatile("cp.async.wait_group %0;" :: "n"(N) : "memory");
}
__device__ __forceinline__ void ldsm4(uint32_t r[4], uint32_t addr) {
    asm volatile("ldmatrix.sync.aligned.m8n8.x4.shared.b16 {%0,%1,%2,%3}, [%4];"
                 : "=r"(r[0]), "=r"(r[1]), "=r"(r[2]), "=r"(r[3]) : "r"(addr));
}
__device__ __forceinline__ void mma_f16(float c[4], const uint32_t a[4],
                                        uint32_t b0, uint32_t b1) {
    asm volatile(
        "mma.sync.aligned.m16n8k16.row.col.f32.f16.f16.f32 "
        "{%0,%1,%2,%3}, {%4,%5,%6,%7}, {%8,%9}, {%0,%1,%2,%3};"
        : "+f"(c[0]), "+f"(c[1]), "+f"(c[2]), "+f"(c[3])
        : "r"(a[0]), "r"(a[1]), "r"(a[2]), "r"(a[3]), "r"(b0), "r"(b1));
}
__device__ __forceinline__ uint32_t packh2(float a, float b) {
    __half2 h = __floats2half2_rn(a, b);
    return *(uint32_t*)&h;
}

#define SWZ(x) ((x) ^ (((x) >> 3) & 0x70))

// ---------------------------------------------------------------------------
// fp16 GEMM, weights split: C[M,N] = A[M,K] @ (Bhi+Blo)^T   (B stored [N,K])
// Block 128x128x64, 256 thr (8 warps 2x4), warp tile 64x32, 4-stage cp.async.
// 2 products per accumulator (A*Bhi, A*Blo).
// ---------------------------------------------------------------------------
static constexpr int GEMM_STAGE = 49152;           // A 16KB + Bhi 16KB + Blo 16KB
static constexpr int GEMM_SMEM  = 4 * GEMM_STAGE;  // 196608

template <int RELU, int OUT_HALF>
__global__ __launch_bounds__(256, 1)
void gemm_mma(const __half* __restrict__ A,
              const __half* __restrict__ Bhi, const __half* __restrict__ Blo,
              const float* __restrict__ bias, const float* __restrict__ res,
              float* __restrict__ Cf, __half* __restrict__ Oh,
              float oscale, int N, int K) {
    extern __shared__ __align__(1024) char smem[];
    const uint32_t sb = smem_u32(smem);
    const int tid = threadIdx.x;
    const int lane = tid & 31;
    const int wid = tid >> 5;
    const int warp_m = wid >> 2;
    const int warp_n = wid & 3;
    const int n0 = blockIdx.x * 128;
    const int m0 = blockIdx.y * 128;
    const int nc = K >> 6;

    const int lrow = tid >> 1;
    const int lhalf = (tid & 1) * 64;
    const char* pa  = (const char*)(A   + (size_t)(m0 + lrow) * K) + lhalf;
    const char* pbh = (const char*)(Bhi + (size_t)(n0 + lrow) * K) + lhalf;
    const char* pbl = (const char*)(Blo + (size_t)(n0 + lrow) * K) + lhalf;

    auto issue = [&](int c) {
        uint32_t base = sb + (uint32_t)(c & 3) * GEMM_STAGE;
        size_t koff = (size_t)(c << 6) * 2;
#pragma unroll
        for (int j = 0; j < 4; j++) {
            uint32_t so = SWZ((uint32_t)(lrow * 128 + lhalf + j * 16));
            cp16(base + so,         pa  + koff + j * 16);
            cp16(base + 16384 + so, pbh + koff + j * 16);
            cp16(base + 32768 + so, pbl + koff + j * 16);
        }
        cp_commit();
    };

    issue(0);
    if (nc > 1) issue(1);
    if (nc > 2) issue(2);

    const int rowA = (lane & 7) + ((lane >> 3) & 1) * 8;
    const int colA = (lane >> 4) * 16;
    const int rowB = (lane & 7) + (lane >> 4) * 8;
    const int colB = ((lane >> 3) & 1) * 16;

    float acc[4][4][4];
#pragma unroll
    for (int a = 0; a < 4; a++)
#pragma unroll
        for (int b = 0; b < 4; b++)
#pragma unroll
            for (int r = 0; r < 4; r++) acc[a][b][r] = 0.f;

    uint32_t ah[2][4][4], bh[2][2][4], bl[2][2][4];

    auto load_frag = [&](uint32_t stb, int ks, int buf) {
#pragma unroll
        for (int mt = 0; mt < 4; mt++) {
            uint32_t sw = SWZ((uint32_t)((warp_m * 64 + mt * 16 + rowA) * 128 + ks * 32 + colA));
            ldsm4(ah[buf][mt], stb + sw);
        }
#pragma unroll
        for (int np = 0; np < 2; np++) {
            uint32_t sw = SWZ((uint32_t)((warp_n * 32 + np * 16 + rowB) * 128 + ks * 32 + colB));
            ldsm4(bh[buf][np], stb + 16384 + sw);
            ldsm4(bl[buf][np], stb + 32768 + sw);
        }
    };

    for (int c = 0; c < nc; c++) {
        int rem = nc - c - 1;
        if (rem >= 2) cp_wait<2>(); else if (rem == 1) cp_wait<1>(); else cp_wait<0>();
        __syncthreads();
        if (c + 3 < nc) issue(c + 3);

        uint32_t stb = sb + (uint32_t)(c & 3) * GEMM_STAGE;
        load_frag(stb, 0, 0);
#pragma unroll
        for (int ks = 0; ks < 4; ks++) {
            const int cur = ks & 1;
            if (ks < 3) load_frag(stb, ks + 1, cur ^ 1);
#pragma unroll
            for (int mt = 0; mt < 4; mt++)
#pragma unroll
                for (int nt = 0; nt < 4; nt++)
                    mma_f16(acc[mt][nt], ah[cur][mt],
                            bh[cur][nt >> 1][(nt & 1) * 2], bh[cur][nt >> 1][(nt & 1) * 2 + 1]);
#pragma unroll
            for (int mt = 0; mt < 4; mt++)
#pragma unroll
                for (int nt = 0; nt < 4; nt++)
                    mma_f16(acc[mt][nt], ah[cur][mt],
                            bl[cur][nt >> 1][(nt & 1) * 2], bl[cur][nt >> 1][(nt & 1) * 2 + 1]);
        }
    }

    const int rbase = m0 + warp_m * 64 + (lane >> 2);
    const int cbase = n0 + warp_n * 32 + (lane & 3) * 2;
#pragma unroll
    for (int mt = 0; mt < 4; mt++) {
#pragma unroll
        for (int nt = 0; nt < 4; nt++) {
            int col = cbase + nt * 8;
#pragma unroll
            for (int half = 0; half < 2; half++) {
                int row = rbase + mt * 16 + half * 8;
                float v0 = acc[mt][nt][half * 2 + 0];
                float v1 = acc[mt][nt][half * 2 + 1];
                if (bias) {
                    float2 b2 = *(const float2*)(bias + col);
                    v0 += b2.x; v1 += b2.y;
                }
                if (res) {
                    float2 r2 = *(const float2*)(res + (size_t)row * N + col);
                    v0 += r2.x; v1 += r2.y;
                }
                if (RELU) { v0 = fmaxf(v0, 0.f); v1 = fmaxf(v1, 0.f); }
                if (OUT_HALF) {
                    v0 *= oscale; v1 *= oscale;
                    __half2 h = __floats2half2_rn(v0, v1);
                    *(__half2*)(Oh + (size_t)row * N + col) = h;
                } else {
                    float2 o2; o2.x = v0; o2.y = v1;
                    *(float2*)(Cf + (size_t)row * N + col) = o2;
                }
            }
        }
    }
}

// ---------------------------------------------------------------------------
// LayerNorm -> fp16 output. One block per row, 256 threads.
// ---------------------------------------------------------------------------
__global__ void ln_half(const float* __restrict__ x, const float* __restrict__ g,
                        const float* __restrict__ b, __half* __restrict__ o) {
    int row = blockIdx.x;
    int tid = threadIdx.x;
    const float4* xr = (const float4*)(x + (size_t)row * C_DIM);
    float4 v = xr[tid];
    float s = v.x + v.y + v.z + v.w;
    float q = v.x * v.x + v.y * v.y + v.z * v.z + v.w * v.w;
#pragma unroll
    for (int of = 16; of > 0; of >>= 1) {
        s += __shfl_xor_sync(0xffffffffu, s, of);
        q += __shfl_xor_sync(0xffffffffu, q, of);
    }
    __shared__ float ss[8], qs[8];
    if ((tid & 31) == 0) { ss[tid >> 5] = s; qs[tid >> 5] = q; }
    __syncthreads();
    float ts = 0.f, tq = 0.f;
#pragma unroll
    for (int i = 0; i < 8; i++) { ts += ss[i]; tq += qs[i]; }
    float mu = ts * (1.0f / C_DIM);
    float var = tq * (1.0f / C_DIM) - mu * mu;
    float rstd = rsqrtf(var + 1e-5f);
    float4 gg = ((const float4*)g)[tid];
    float4 bb = ((const float4*)b)[tid];
    float o0 = (v.x - mu) * rstd * gg.x + bb.x;
    float o1 = (v.y - mu) * rstd * gg.y + bb.y;
    float o2 = (v.z - mu) * rstd * gg.z + bb.z;
    float o3 = (v.w - mu) * rstd * gg.w + bb.w;
    __half2* po = (__half2*)(o + (size_t)row * C_DIM);
    po[tid * 2]     = __floats2half2_rn(o0, o1);
    po[tid * 2 + 1] = __floats2half2_rn(o2, o3);
}

// weight transpose+split: W[K,N] -> T[N,K] fp16 hi/lo
__global__ void wsplit_t(const float* __restrict__ W, __half* __restrict__ Thi,
                         __half* __restrict__ Tlo, int K, int N) {
    __shared__ float t[32][33];
    int n0 = blockIdx.x * 32, k0 = blockIdx.y * 32;
    int tx = threadIdx.x, ty = threadIdx.y;  // 32x8
#pragma unroll
    for (int i = 0; i < 32; i += 8) t[ty + i][tx] = W[(size_t)(k0 + ty + i) * N + n0 + tx];
    __syncthreads();
#pragma unroll
    for (int i = 0; i < 32; i += 8) {
        float v = t[tx][ty + i];
        __half h = __float2half_rn(v);
        __half l = __float2half_rn(v - __half2float(h));
        size_t o = (size_t)(n0 + ty + i) * K + k0 + tx;
        Thi[o] = h;
        Tlo[o] = l;
    }
}

// ---------------------------------------------------------------------------
// Flash attention on mma.sync fp16. Block = 4 warps, 64 q-rows.
// Warp w owns q rows [w*16, w*16+16). S and PV via m16n8k16.
// Q pre-scaled by 1/8 in the Q projection. Output fp16 (feeds Wo GEMM).
// ---------------------------------------------------------------------------
struct ASmem {
    __half Qs[64 * 64];   // swizzled 128B rows: [qrow][d]
    __half Ks[64 * 64];   // [kpos][d]
    __half Vt[64 * 64];   // transposed: [d][kpos]
};

__global__ __launch_bounds__(128, 3)
void attn_mma(const __half* __restrict__ Qg, const __half* __restrict__ Kg,
              const __half* __restrict__ Vg, __half* __restrict__ Og) {
    __shared__ ASmem s;
    const int qt = blockIdx.x, h = blockIdx.y, b = blockIdx.z;
    const int tid = threadIdx.x;
    const int lane = tid & 31;
    const int w = tid >> 5;

    const uint32_t sq = smem_u32(s.Qs);
    const uint32_t sk = smem_u32(s.Ks);
    char* svp = (char*)s.Vt;

    const int rowA = (lane & 7) + ((lane >> 3) & 1) * 8;
    const int colA = (lane >> 4) * 16;
    const int rowB = (lane & 7) + (lane >> 4) * 8;
    const int colB = ((lane >> 3) & 1) * 16;

    // load Q tile (64 rows x 128B)
    {
        int r = tid >> 1, hh = (tid & 1) * 64;
        const char* src = (const char*)(Qg + ((size_t)(b * T_SEQ + qt * 64 + r)) * C_DIM + h * D_HEAD) + hh;
#pragma unroll
        for (int j = 0; j < 4; j++)
            cp16(sq + SWZ((uint32_t)(r * 128 + hh + j * 16)), src + j * 16);
        cp_commit();
    }
    cp_wait<0>();
    __syncthreads();

    // Q fragments (fixed for whole block)
    uint32_t qa[4][4];
#pragma unroll
    for (int ks = 0; ks < 4; ks++)
        ldsm4(qa[ks], sq + SWZ((uint32_t)((w * 16 + rowA) * 128 + ks * 32 + colA)));

    float m0 = -1e30f, m1 = -1e30f, l0 = 0.f, l1 = 0.f;
    float oacc[8][4];
#pragma unroll
    for (int nt = 0; nt < 8; nt++)
#pragma unroll
        for (int r = 0; r < 4; r++) oacc[nt][r] = 0.f;

    for (int kt = 0; kt <= qt; kt++) {
        __syncthreads();  // previous iteration's reads done before overwrite
        // K tile via cp.async
        {
            int r = tid >> 1, hh = (tid & 1) * 64;
            const char* src = (const char*)(Kg + ((size_t)(b * T_SEQ + kt * 64 + r)) * C_DIM + h * D_HEAD) + hh;
#pragma unroll
            for (int j = 0; j < 4; j++)
                cp16(sk + SWZ((uint32_t)(r * 128 + hh + j * 16)), src + j * 16);
            cp_commit();
        }
        // V tile transposed: thread handles kpos pair (kp, kp+1), 16 d values
        {
            int kp = (tid & 31) * 2;
            int d0 = (tid >> 5) * 16;
            const uint4* p0 = (const uint4*)(Vg + ((size_t)(b * T_SEQ + kt * 64 + kp)) * C_DIM + h * D_HEAD + d0);
            const uint4* p1 = (const uint4*)(Vg + ((size_t)(b * T_SEQ + kt * 64 + kp + 1)) * C_DIM + h * D_HEAD + d0);
            __half a0[16], a1[16];
            *(uint4*)(a0) = p0[0]; *(uint4*)(a0 + 8) = p0[1];
            *(uint4*)(a1) = p1[0]; *(uint4*)(a1 + 8) = p1[1];
#pragma unroll
            for (int i = 0; i < 16; i++) {
                int d = d0 + i;
                *(__half2*)(svp + SWZ((uint32_t)(d * 128 + kp * 2))) = __halves2half2(a0[i], a1[i]);
            }
        }
        cp_wait<0>();
        __syncthreads();

        // S = Q @ K^T
        float sacc[8][4];
#pragma unroll
        for (int nt = 0; nt < 8; nt++)
#pragma unroll
            for (int r = 0; r < 4; r++) sacc[nt][r] = 0.f;
#pragma unroll
        for (int ks = 0; ks < 4; ks++) {
            uint32_t kb[4][4];
#pragma unroll
            for (int p = 0; p < 4; p++)
                ldsm4(kb[p], sk + SWZ((uint32_t)((p * 16 + rowB) * 128 + ks * 32 + colB)));
#pragma unroll
            for (int nt = 0; nt < 8; nt++)
                mma_f16(sacc[nt], qa[ks], kb[nt >> 1][(nt & 1) * 2], kb[nt >> 1][(nt & 1) * 2 + 1]);
        }

        // causal mask on diagonal tile
        if (kt == qt) {
            int rl0 = w * 16 + (lane >> 2);
            int rl1 = rl0 + 8;
#pragma unroll
            for (int nt = 0; nt < 8; nt++) {
                int cl = nt * 8 + 2 * (lane & 3);
                if (cl > rl0)     sacc[nt][0] = -1e30f;
                if (cl + 1 > rl0) sacc[nt][1] = -1e30f;
                if (cl > rl1)     sacc[nt][2] = -1e30f;
                if (cl + 1 > rl1) sacc[nt][3] = -1e30f;
            }
        }

        // row max (across 8 tiles, then across the quad)
        float mx0 = -1e30f, mx1 = -1e30f;
#pragma unroll
        for (int nt = 0; nt < 8; nt++) {
            mx0 = fmaxf(mx0, fmaxf(sacc[nt][0], sacc[nt][1]));
            mx1 = fmaxf(mx1, fmaxf(sacc[nt][2], sacc[nt][3]));
        }
        mx0 = fmaxf(mx0, __shfl_xor_sync(0xffffffffu, mx0, 1));
        mx0 = fmaxf(mx0, __shfl_xor_sync(0xffffffffu, mx0, 2));
        mx1 = fmaxf(mx1, __shfl_xor_sync(0xffffffffu, mx1, 1));
        mx1 = fmaxf(mx1, __shfl_xor_sync(0xffffffffu, mx1, 2));
        float mn0 = fmaxf(m0, mx0), mn1 = fmaxf(m1, mx1);
        float al0 = __expf(m0 - mn0), al1 = __expf(m1 - mn1);
        m0 = mn0; m1 = mn1;

        // P = exp(S - m); row sums
        float s0 = 0.f, s1 = 0.f;
#pragma unroll
        for (int nt = 0; nt < 8; nt++) {
            sacc[nt][0] = __expf(sacc[nt][0] - mn0);
            sacc[nt][1] = __expf(sacc[nt][1] - mn0);
            sacc[nt][2] = __expf(sacc[nt][2] - mn1);
            sacc[nt][3] = __expf(sacc[nt][3] - mn1);
            s0 += sacc[nt][0] + sacc[nt][1];
            s1 += sacc[nt][2] + sacc[nt][3];
        }
        s0 += __shfl_xor_sync(0xffffffffu, s0, 1);
        s0 += __shfl_xor_sync(0xffffffffu, s0, 2);
        s1 += __shfl_xor_sync(0xffffffffu, s1, 1);
        s1 += __shfl_xor_sync(0xffffffffu, s1, 2);
        l0 = l0 * al0 + s0;
        l1 = l1 * al1 + s1;

        // rescale O
#pragma unroll
        for (int nt = 0; nt < 8; nt++) {
            oacc[nt][0] *= al0; oacc[nt][1] *= al0;
            oacc[nt][2] *= al1; oacc[nt][3] *= al1;
        }

        // P fragments (S accum layout == A fragment layout)
        uint32_t pa[4][4];
#pragma unroll
        for (int ks = 0; ks < 4; ks++) {
            pa[ks][0] = packh2(sacc[2 * ks][0], sacc[2 * ks][1]);
            pa[ks][1] = packh2(sacc[2 * ks][2], sacc[2 * ks][3]);
            pa[ks][2] = packh2(sacc[2 * ks + 1][0], sacc[2 * ks + 1][1]);
            pa[ks][3] = packh2(sacc[2 * ks + 1][2], sacc[2 * ks + 1][3]);
        }

        // O += P @ V  (B from transposed V, GEMM-B pattern)
        const uint32_t sv = smem_u32(s.Vt);
#pragma unroll
        for (int ks = 0; ks < 4; ks++) {
            uint32_t vb[4][4];
#pragma unroll
            for (int p = 0; p < 4; p++)
                ldsm4(vb[p], sv + SWZ((uint32_t)((p * 16 + rowB) * 128 + ks * 32 + colB)));
#pragma unroll
            for (int nt = 0; nt < 8; nt++)
                mma_f16(oacc[nt], pa[ks], vb[nt >> 1][(nt & 1) * 2], vb[nt >> 1][(nt & 1) * 2 + 1]);
        }
    }

    // write O / l  (fp16, feeds Wo GEMM)
    float inv0 = 1.0f / l0, inv1 = 1.0f / l1;
    int row0 = qt * 64 + w * 16 + (lane >> 2);
    int row1 = row0 + 8;
#pragma unroll
    for (int nt = 0; nt < 8; nt++) {
        int col = h * D_HEAD + nt * 8 + 2 * (lane & 3);
        *(__half2*)(Og + ((size_t)(b * T_SEQ + row0)) * C_DIM + col) =
            __floats2half2_rn(oacc[nt][0] * inv0, oacc[nt][1] * inv0);
        *(__half2*)(Og + ((size_t)(b * T_SEQ + row1)) * C_DIM + col) =
            __floats2half2_rn(oacc[nt][2] * inv1, oacc[nt][3] * inv1);
    }
}

// ---------------------------------------------------------------------------
// Launch
// ---------------------------------------------------------------------------
extern "C" void kernel_launch(void* const* d_in, const int* in_sizes, int n_in,
                              void* d_out, int out_size) {
    const float* x    = (const float*)d_in[0];
    const float* Wq   = (const float*)d_in[1];
    const float* Wk   = (const float*)d_in[2];
    const float* Wv   = (const float*)d_in[3];
    const float* Wo   = (const float*)d_in[4];
    const float* bo   = (const float*)d_in[5];
    const float* ln1g = (const float*)d_in[6];
    const float* ln1b = (const float*)d_in[7];
    const float* ln2g = (const float*)d_in[8];
    const float* ln2b = (const float*)d_in[9];
    const float* W1   = (const float*)d_in[10];
    const float* b1   = (const float*)d_in[11];
    const float* W2   = (const float*)d_in[12];
    const float* b2   = (const float*)d_in[13];
    float* out = (float*)d_out;

    __half *a, *qh, *kh, *vh, *at, *ffh;
    float* x2;
    __half *wqh, *wql, *wkh, *wkl, *wvh, *wvl, *woh, *wol, *w1h, *w1l, *w2h, *w2l;
    cudaGetSymbolAddress((void**)&a,   g_a);
    cudaGetSymbolAddress((void**)&qh,  g_qh);
    cudaGetSymbolAddress((void**)&kh,  g_kh);
    cudaGetSymbolAddress((void**)&vh,  g_vh);
    cudaGetSymbolAddress((void**)&at,  g_at);
    cudaGetSymbolAddress((void**)&ffh, g_ffh);
    cudaGetSymbolAddress((void**)&x2,  g_x2);
    cudaGetSymbolAddress((void**)&wqh, g_wqh); cudaGetSymbolAddress((void**)&wql, g_wql);
    cudaGetSymbolAddress((void**)&wkh, g_wkh); cudaGetSymbolAddress((void**)&wkl, g_wkl);
    cudaGetSymbolAddress((void**)&wvh, g_wvh); cudaGetSymbolAddress((void**)&wvl, g_wvl);
    cudaGetSymbolAddress((void**)&woh, g_woh); cudaGetSymbolAddress((void**)&wol, g_wol);
    cudaGetSymbolAddress((void**)&w1h, g_w1h); cudaGetSymbolAddress((void**)&w1l, g_w1l);
    cudaGetSymbolAddress((void**)&w2h, g_w2h); cudaGetSymbolAddress((void**)&w2l, g_w2l);

    cudaFuncSetAttribute(gemm_mma<0, 0>, cudaFuncAttributeMaxDynamicSharedMemorySize, GEMM_SMEM);
    cudaFuncSetAttribute(gemm_mma<0, 1>, cudaFuncAttributeMaxDynamicSharedMemorySize, GEMM_SMEM);
    cudaFuncSetAttribute(gemm_mma<1, 1>, cudaFuncAttributeMaxDynamicSharedMemorySize, GEMM_SMEM);

    dim3 wblk(32, 8);
    dim3 g1024(C_DIM / 128, M_ROWS / 128);
    dim3 g4096(FF_DIM / 128, M_ROWS / 128);

    // #1-#3: QKV weight transpose + split
    wsplit_t<<<dim3(C_DIM / 32, C_DIM / 32), wblk>>>(Wq, wqh, wql, C_DIM, C_DIM);
    wsplit_t<<<dim3(C_DIM / 32, C_DIM / 32), wblk>>>(Wk, wkh, wkl, C_DIM, C_DIM);
    wsplit_t<<<dim3(C_DIM / 32, C_DIM / 32), wblk>>>(Wv, wvh, wvl, C_DIM, C_DIM);
    // #4: ln1 -> fp16 activations
    ln_half<<<M_ROWS, 256>>>(x, ln1g, ln1b, a);
    // #5: Q projection (scaled by 1/8, fp16 out)
    gemm_mma<0, 1><<<g1024, 256, GEMM_SMEM>>>(a, wqh, wql, nullptr, nullptr,
                                              nullptr, qh, 0.125f, C_DIM, C_DIM);
    // #6: K projection
    gemm_mma<0, 1><<<g1024, 256, GEMM_SMEM>>>(a, wkh, wkl, nullptr, nullptr,
                                              nullptr, kh, 1.0f, C_DIM, C_DIM);
    // #7: V projection
    gemm_mma<0, 1><<<g1024, 256, GEMM_SMEM>>>(a, wvh, wvl, nullptr, nullptr,
                                              nullptr, vh, 1.0f, C_DIM, C_DIM);
    // #8-#10: remaining weight splits
    wsplit_t<<<dim3(C_DIM / 32, C_DIM / 32), wblk>>>(Wo, woh, wol, C_DIM, C_DIM);
    wsplit_t<<<dim3(FF_DIM / 32, C_DIM / 32), wblk>>>(W1, w1h, w1l, C_DIM, FF_DIM);
    wsplit_t<<<dim3(C_DIM / 32, FF_DIM / 32), wblk>>>(W2, w2h, w2l, FF_DIM, C_DIM);
    // #11: flash attention (fp16 tensor cores), fp16 out
    attn_mma<<<dim3(T_SEQ / 64, H_NUM, B_NUM), 128>>>(qh, kh, vh, at);
    // #12: Wo projection + bias + residual -> x2 (fp32)
    gemm_mma<0, 0><<<g1024, 256, GEMM_SMEM>>>(at, woh, wol, bo, x,
                                              x2, nullptr, 1.0f, C_DIM, C_DIM);
    // #13: ln2 -> fp16
    ln_half<<<M_ROWS, 256>>>(x2, ln2g, ln2b, a);
    // #14: MLP up + bias + ReLU (fp16 out)
    gemm_mma<1, 1><<<g4096, 256, GEMM_SMEM>>>(a, w1h, w1l, b1, nullptr,
                                              nullptr, ffh, 1.0f, FF_DIM, C_DIM);
    // #15: MLP down + bias + residual -> out (fp32)
    gemm_mma<0, 0><<<g1024, 256, GEMM_SMEM>>>(ffh, w2h, w2l, b2, x2,
                                              out, nullptr, 1.0f, C_DIM, FF_DIM);
}

// round 6
// speedup vs baseline: 3.5059x; 1.7038x over previous
#include <cuda_runtime.h>
#include <cuda_fp16.h>
#include <math.h>
#include <cstdint>

// ---------------------------------------------------------------------------
// MiniBlock: x + attn(ln1(x)); then + mlp(ln2(.))
// B=4, T=2048, C=1024, H=16, D=64, FF=4096.
// GEMMs: mma.sync fp16, single product (weights + activations fp16).
// Attention: flash, fully on mma.sync fp16.
// ---------------------------------------------------------------------------

#define B_NUM 4
#define T_SEQ 2048
#define C_DIM 1024
#define H_NUM 16
#define D_HEAD 64
#define FF_DIM 4096
#define M_ROWS (B_NUM * T_SEQ)   // 8192

// ---------------- scratch (device globals) ----------------------------------
__device__ __half g_a  [M_ROWS * C_DIM];   // ln output (fp16 activations)
__device__ __half g_qh [M_ROWS * C_DIM];
__device__ __half g_kh [M_ROWS * C_DIM];
__device__ __half g_vh [M_ROWS * C_DIM];
__device__ __half g_at [M_ROWS * C_DIM];   // attention output
__device__ __half g_ffh[M_ROWS * FF_DIM];
__device__ float  g_x2 [M_ROWS * C_DIM];

__device__ __half g_wq[C_DIM * C_DIM];
__device__ __half g_wk[C_DIM * C_DIM];
__device__ __half g_wv[C_DIM * C_DIM];
__device__ __half g_wo[C_DIM * C_DIM];
__device__ __half g_w1[FF_DIM * C_DIM];
__device__ __half g_w2[C_DIM * FF_DIM];

// ---------------- PTX helpers ------------------------------------------------
__device__ __forceinline__ uint32_t smem_u32(const void* p) {
    uint32_t a;
    asm("{ .reg .u64 t; cvta.to.shared.u64 t, %1; cvt.u32.u64 %0, t; }" : "=r"(a) : "l"(p));
    return a;
}
__device__ __forceinline__ void cp16(uint32_t dst, const void* src) {
    asm volatile("cp.async.cg.shared.global [%0], [%1], 16;" :: "r"(dst), "l"(src));
}
__device__ __forceinline__ void cp_commit() { asm volatile("cp.async.commit_group;" ::: "memory"); }
template <int N> __device__ __forceinline__ void cp_wait() {
    asm volatile("cp.async.wait_group %0;" :: "n"(N) : "memory");
}
__device__ __forceinline__ void ldsm4(uint32_t r[4], uint32_t addr) {
    asm volatile("ldmatrix.sync.aligned.m8n8.x4.shared.b16 {%0,%1,%2,%3}, [%4];"
                 : "=r"(r[0]), "=r"(r[1]), "=r"(r[2]), "=r"(r[3]) : "r"(addr));
}
__device__ __forceinline__ void mma_f16(float c[4], const uint32_t a[4],
                                        uint32_t b0, uint32_t b1) {
    asm volatile(
        "mma.sync.aligned.m16n8k16.row.col.f32.f16.f16.f32 "
        "{%0,%1,%2,%3}, {%4,%5,%6,%7}, {%8,%9}, {%0,%1,%2,%3};"
        : "+f"(c[0]), "+f"(c[1]), "+f"(c[2]), "+f"(c[3])
        : "r"(a[0]), "r"(a[1]), "r"(a[2]), "r"(a[3]), "r"(b0), "r"(b1));
}
__device__ __forceinline__ uint32_t packh2(float a, float b) {
    __half2 h = __floats2half2_rn(a, b);
    return *(uint32_t*)&h;
}

#define SWZ(x) ((x) ^ (((x) >> 3) & 0x70))

// ---------------------------------------------------------------------------
// fp16 GEMM: C[M,N] = A[M,K] @ B^T   (B stored [N,K] fp16)
// Block 128x128x64, 256 thr (8 warps 2x4), warp tile 64x32.
// 3-stage cp.async pipeline, 2 CTAs/SM.
// ---------------------------------------------------------------------------
static constexpr int GEMM_STAGE = 32768;           // A 16KB + B 16KB
static constexpr int GEMM_SMEM  = 3 * GEMM_STAGE;  // 98304

template <int RELU, int OUT_HALF>
__global__ __launch_bounds__(256, 2)
void gemm_mma(const __half* __restrict__ A, const __half* __restrict__ B,
              const float* __restrict__ bias, const float* __restrict__ res,
              float* __restrict__ Cf, __half* __restrict__ Oh,
              float oscale, int N, int K) {
    extern __shared__ __align__(1024) char smem[];
    const uint32_t sb = smem_u32(smem);
    const int tid = threadIdx.x;
    const int lane = tid & 31;
    const int wid = tid >> 5;
    const int warp_m = wid >> 2;
    const int warp_n = wid & 3;
    const int n0 = blockIdx.x * 128;
    const int m0 = blockIdx.y * 128;
    const int nc = K >> 6;

    const int lrow = tid >> 1;
    const int lhalf = (tid & 1) * 64;
    const char* pa = (const char*)(A + (size_t)(m0 + lrow) * K) + lhalf;
    const char* pb = (const char*)(B + (size_t)(n0 + lrow) * K) + lhalf;

    auto issue = [&](int c) {
        uint32_t base = sb + (uint32_t)(c % 3) * GEMM_STAGE;
        size_t koff = (size_t)(c << 6) * 2;
#pragma unroll
        for (int j = 0; j < 4; j++) {
            uint32_t so = SWZ((uint32_t)(lrow * 128 + lhalf + j * 16));
            cp16(base + so,         pa + koff + j * 16);
            cp16(base + 16384 + so, pb + koff + j * 16);
        }
        cp_commit();
    };

    issue(0);
    if (nc > 1) issue(1);

    const int rowA = (lane & 7) + ((lane >> 3) & 1) * 8;
    const int colA = (lane >> 4) * 16;
    const int rowB = (lane & 7) + (lane >> 4) * 8;
    const int colB = ((lane >> 3) & 1) * 16;

    float acc[4][4][4];
#pragma unroll
    for (int a = 0; a < 4; a++)
#pragma unroll
        for (int b = 0; b < 4; b++)
#pragma unroll
            for (int r = 0; r < 4; r++) acc[a][b][r] = 0.f;

    for (int c = 0; c < nc; c++) {
        if (c + 1 < nc) cp_wait<1>(); else cp_wait<0>();
        __syncthreads();
        if (c + 2 < nc) issue(c + 2);

        uint32_t stb = sb + (uint32_t)(c % 3) * GEMM_STAGE;
#pragma unroll
        for (int ks = 0; ks < 4; ks++) {
            uint32_t ah[4][4], bh[2][4];
#pragma unroll
            for (int mt = 0; mt < 4; mt++) {
                uint32_t sw = SWZ((uint32_t)((warp_m * 64 + mt * 16 + rowA) * 128 + ks * 32 + colA));
                ldsm4(ah[mt], stb + sw);
            }
#pragma unroll
            for (int np = 0; np < 2; np++) {
                uint32_t sw = SWZ((uint32_t)((warp_n * 32 + np * 16 + rowB) * 128 + ks * 32 + colB));
                ldsm4(bh[np], stb + 16384 + sw);
            }
#pragma unroll
            for (int mt = 0; mt < 4; mt++)
#pragma unroll
                for (int nt = 0; nt < 4; nt++)
                    mma_f16(acc[mt][nt], ah[mt],
                            bh[nt >> 1][(nt & 1) * 2], bh[nt >> 1][(nt & 1) * 2 + 1]);
        }
    }

    const int rbase = m0 + warp_m * 64 + (lane >> 2);
    const int cbase = n0 + warp_n * 32 + (lane & 3) * 2;
#pragma unroll
    for (int mt = 0; mt < 4; mt++) {
#pragma unroll
        for (int nt = 0; nt < 4; nt++) {
            int col = cbase + nt * 8;
#pragma unroll
            for (int half = 0; half < 2; half++) {
                int row = rbase + mt * 16 + half * 8;
                float v0 = acc[mt][nt][half * 2 + 0];
                float v1 = acc[mt][nt][half * 2 + 1];
                if (bias) {
                    float2 b2 = *(const float2*)(bias + col);
                    v0 += b2.x; v1 += b2.y;
                }
                if (res) {
                    float2 r2 = *(const float2*)(res + (size_t)row * N + col);
                    v0 += r2.x; v1 += r2.y;
                }
                if (RELU) { v0 = fmaxf(v0, 0.f); v1 = fmaxf(v1, 0.f); }
                if (OUT_HALF) {
                    v0 *= oscale; v1 *= oscale;
                    __half2 h = __floats2half2_rn(v0, v1);
                    *(__half2*)(Oh + (size_t)row * N + col) = h;
                } else {
                    float2 o2; o2.x = v0; o2.y = v1;
                    *(float2*)(Cf + (size_t)row * N + col) = o2;
                }
            }
        }
    }
}

// ---------------------------------------------------------------------------
// LayerNorm -> fp16 output. One block per row, 256 threads.
// ---------------------------------------------------------------------------
__global__ void ln_half(const float* __restrict__ x, const float* __restrict__ g,
                        const float* __restrict__ b, __half* __restrict__ o) {
    int row = blockIdx.x;
    int tid = threadIdx.x;
    const float4* xr = (const float4*)(x + (size_t)row * C_DIM);
    float4 v = xr[tid];
    float s = v.x + v.y + v.z + v.w;
    float q = v.x * v.x + v.y * v.y + v.z * v.z + v.w * v.w;
#pragma unroll
    for (int of = 16; of > 0; of >>= 1) {
        s += __shfl_xor_sync(0xffffffffu, s, of);
        q += __shfl_xor_sync(0xffffffffu, q, of);
    }
    __shared__ float ss[8], qs[8];
    if ((tid & 31) == 0) { ss[tid >> 5] = s; qs[tid >> 5] = q; }
    __syncthreads();
    float ts = 0.f, tq = 0.f;
#pragma unroll
    for (int i = 0; i < 8; i++) { ts += ss[i]; tq += qs[i]; }
    float mu = ts * (1.0f / C_DIM);
    float var = tq * (1.0f / C_DIM) - mu * mu;
    float rstd = rsqrtf(var + 1e-5f);
    float4 gg = ((const float4*)g)[tid];
    float4 bb = ((const float4*)b)[tid];
    float o0 = (v.x - mu) * rstd * gg.x + bb.x;
    float o1 = (v.y - mu) * rstd * gg.y + bb.y;
    float o2 = (v.z - mu) * rstd * gg.z + bb.z;
    float o3 = (v.w - mu) * rstd * gg.w + bb.w;
    __half2* po = (__half2*)(o + (size_t)row * C_DIM);
    po[tid * 2]     = __floats2half2_rn(o0, o1);
    po[tid * 2 + 1] = __floats2half2_rn(o2, o3);
}

// weight transpose: W[K,N] -> T[N,K] fp16
__global__ void wtrans(const float* __restrict__ W, __half* __restrict__ T,
                       int K, int N) {
    __shared__ float t[32][33];
    int n0 = blockIdx.x * 32, k0 = blockIdx.y * 32;
    int tx = threadIdx.x, ty = threadIdx.y;  // 32x8
#pragma unroll
    for (int i = 0; i < 32; i += 8) t[ty + i][tx] = W[(size_t)(k0 + ty + i) * N + n0 + tx];
    __syncthreads();
#pragma unroll
    for (int i = 0; i < 32; i += 8) {
        size_t o = (size_t)(n0 + ty + i) * K + k0 + tx;
        T[o] = __float2half_rn(t[tx][ty + i]);
    }
}

// ---------------------------------------------------------------------------
// Flash attention on mma.sync fp16. Block = 4 warps, 64 q-rows.
// qt remapped for load balance. Q pre-scaled by 1/8. Output fp16.
// ---------------------------------------------------------------------------
struct ASmem {
    __half Qs[64 * 64];
    __half Ks[64 * 64];
    __half Vt[64 * 64];
};

__global__ __launch_bounds__(128, 3)
void attn_mma(const __half* __restrict__ Qg, const __half* __restrict__ Kg,
              const __half* __restrict__ Vg, __half* __restrict__ Og) {
    __shared__ ASmem s;
    const int qtx = blockIdx.x;
    const int NT = T_SEQ / 64;  // 32
    const int qt = (qtx & 1) ? (NT - 1 - (qtx >> 1)) : (qtx >> 1);  // balance
    const int h = blockIdx.y, b = blockIdx.z;
    const int tid = threadIdx.x;
    const int lane = tid & 31;
    const int w = tid >> 5;

    const uint32_t sq = smem_u32(s.Qs);
    const uint32_t sk = smem_u32(s.Ks);
    char* svp = (char*)s.Vt;

    const int rowA = (lane & 7) + ((lane >> 3) & 1) * 8;
    const int colA = (lane >> 4) * 16;
    const int rowB = (lane & 7) + (lane >> 4) * 8;
    const int colB = ((lane >> 3) & 1) * 16;

    {
        int r = tid >> 1, hh = (tid & 1) * 64;
        const char* src = (const char*)(Qg + ((size_t)(b * T_SEQ + qt * 64 + r)) * C_DIM + h * D_HEAD) + hh;
#pragma unroll
        for (int j = 0; j < 4; j++)
            cp16(sq + SWZ((uint32_t)(r * 128 + hh + j * 16)), src + j * 16);
        cp_commit();
    }
    cp_wait<0>();
    __syncthreads();

    uint32_t qa[4][4];
#pragma unroll
    for (int ks = 0; ks < 4; ks++)
        ldsm4(qa[ks], sq + SWZ((uint32_t)((w * 16 + rowA) * 128 + ks * 32 + colA)));

    float m0 = -1e30f, m1 = -1e30f, l0 = 0.f, l1 = 0.f;
    float oacc[8][4];
#pragma unroll
    for (int nt = 0; nt < 8; nt++)
#pragma unroll
        for (int r = 0; r < 4; r++) oacc[nt][r] = 0.f;

    for (int kt = 0; kt <= qt; kt++) {
        __syncthreads();
        {
            int r = tid >> 1, hh = (tid & 1) * 64;
            const char* src = (const char*)(Kg + ((size_t)(b * T_SEQ + kt * 64 + r)) * C_DIM + h * D_HEAD) + hh;
#pragma unroll
            for (int j = 0; j < 4; j++)
                cp16(sk + SWZ((uint32_t)(r * 128 + hh + j * 16)), src + j * 16);
            cp_commit();
        }
        {
            int kp = (tid & 31) * 2;
            int d0 = (tid >> 5) * 16;
            const uint4* p0 = (const uint4*)(Vg + ((size_t)(b * T_SEQ + kt * 64 + kp)) * C_DIM + h * D_HEAD + d0);
            const uint4* p1 = (const uint4*)(Vg + ((size_t)(b * T_SEQ + kt * 64 + kp + 1)) * C_DIM + h * D_HEAD + d0);
            __half a0[16], a1[16];
            *(uint4*)(a0) = p0[0]; *(uint4*)(a0 + 8) = p0[1];
            *(uint4*)(a1) = p1[0]; *(uint4*)(a1 + 8) = p1[1];
#pragma unroll
            for (int i = 0; i < 16; i++) {
                int d = d0 + i;
                *(__half2*)(svp + SWZ((uint32_t)(d * 128 + kp * 2))) = __halves2half2(a0[i], a1[i]);
            }
        }
        cp_wait<0>();
        __syncthreads();

        float sacc[8][4];
#pragma unroll
        for (int nt = 0; nt < 8; nt++)
#pragma unroll
            for (int r = 0; r < 4; r++) sacc[nt][r] = 0.f;
#pragma unroll
        for (int ks = 0; ks < 4; ks++) {
            uint32_t kb[4][4];
#pragma unroll
            for (int p = 0; p < 4; p++)
                ldsm4(kb[p], sk + SWZ((uint32_t)((p * 16 + rowB) * 128 + ks * 32 + colB)));
#pragma unroll
            for (int nt = 0; nt < 8; nt++)
                mma_f16(sacc[nt], qa[ks], kb[nt >> 1][(nt & 1) * 2], kb[nt >> 1][(nt & 1) * 2 + 1]);
        }

        if (kt == qt) {
            int rl0 = w * 16 + (lane >> 2);
            int rl1 = rl0 + 8;
#pragma unroll
            for (int nt = 0; nt < 8; nt++) {
                int cl = nt * 8 + 2 * (lane & 3);
                if (cl > rl0)     sacc[nt][0] = -1e30f;
                if (cl + 1 > rl0) sacc[nt][1] = -1e30f;
                if (cl > rl1)     sacc[nt][2] = -1e30f;
                if (cl + 1 > rl1) sacc[nt][3] = -1e30f;
            }
        }

        float mx0 = -1e30f, mx1 = -1e30f;
#pragma unroll
        for (int nt = 0; nt < 8; nt++) {
            mx0 = fmaxf(mx0, fmaxf(sacc[nt][0], sacc[nt][1]));
            mx1 = fmaxf(mx1, fmaxf(sacc[nt][2], sacc[nt][3]));
        }
        mx0 = fmaxf(mx0, __shfl_xor_sync(0xffffffffu, mx0, 1));
        mx0 = fmaxf(mx0, __shfl_xor_sync(0xffffffffu, mx0, 2));
        mx1 = fmaxf(mx1, __shfl_xor_sync(0xffffffffu, mx1, 1));
        mx1 = fmaxf(mx1, __shfl_xor_sync(0xffffffffu, mx1, 2));
        float mn0 = fmaxf(m0, mx0), mn1 = fmaxf(m1, mx1);
        float al0 = __expf(m0 - mn0), al1 = __expf(m1 - mn1);
        m0 = mn0; m1 = mn1;

        float s0 = 0.f, s1 = 0.f;
#pragma unroll
        for (int nt = 0; nt < 8; nt++) {
            sacc[nt][0] = __expf(sacc[nt][0] - mn0);
            sacc[nt][1] = __expf(sacc[nt][1] - mn0);
            sacc[nt][2] = __expf(sacc[nt][2] - mn1);
            sacc[nt][3] = __expf(sacc[nt][3] - mn1);
            s0 += sacc[nt][0] + sacc[nt][1];
            s1 += sacc[nt][2] + sacc[nt][3];
        }
        s0 += __shfl_xor_sync(0xffffffffu, s0, 1);
        s0 += __shfl_xor_sync(0xffffffffu, s0, 2);
        s1 += __shfl_xor_sync(0xffffffffu, s1, 1);
        s1 += __shfl_xor_sync(0xffffffffu, s1, 2);
        l0 = l0 * al0 + s0;
        l1 = l1 * al1 + s1;

#pragma unroll
        for (int nt = 0; nt < 8; nt++) {
            oacc[nt][0] *= al0; oacc[nt][1] *= al0;
            oacc[nt][2] *= al1; oacc[nt][3] *= al1;
        }

        uint32_t pa[4][4];
#pragma unroll
        for (int ks = 0; ks < 4; ks++) {
            pa[ks][0] = packh2(sacc[2 * ks][0], sacc[2 * ks][1]);
            pa[ks][1] = packh2(sacc[2 * ks][2], sacc[2 * ks][3]);
            pa[ks][2] = packh2(sacc[2 * ks + 1][0], sacc[2 * ks + 1][1]);
            pa[ks][3] = packh2(sacc[2 * ks + 1][2], sacc[2 * ks + 1][3]);
        }

        const uint32_t sv = smem_u32(s.Vt);
#pragma unroll
        for (int ks = 0; ks < 4; ks++) {
            uint32_t vb[4][4];
#pragma unroll
            for (int p = 0; p < 4; p++)
                ldsm4(vb[p], sv + SWZ((uint32_t)((p * 16 + rowB) * 128 + ks * 32 + colB)));
#pragma unroll
            for (int nt = 0; nt < 8; nt++)
                mma_f16(oacc[nt], pa[ks], vb[nt >> 1][(nt & 1) * 2], vb[nt >> 1][(nt & 1) * 2 + 1]);
        }
    }

    float inv0 = 1.0f / l0, inv1 = 1.0f / l1;
    int row0 = qt * 64 + w * 16 + (lane >> 2);
    int row1 = row0 + 8;
#pragma unroll
    for (int nt = 0; nt < 8; nt++) {
        int col = h * D_HEAD + nt * 8 + 2 * (lane & 3);
        *(__half2*)(Og + ((size_t)(b * T_SEQ + row0)) * C_DIM + col) =
            __floats2half2_rn(oacc[nt][0] * inv0, oacc[nt][1] * inv0);
        *(__half2*)(Og + ((size_t)(b * T_SEQ + row1)) * C_DIM + col) =
            __floats2half2_rn(oacc[nt][2] * inv1, oacc[nt][3] * inv1);
    }
}

// ---------------------------------------------------------------------------
// Launch
// ---------------------------------------------------------------------------
extern "C" void kernel_launch(void* const* d_in, const int* in_sizes, int n_in,
                              void* d_out, int out_size) {
    const float* x    = (const float*)d_in[0];
    const float* Wq   = (const float*)d_in[1];
    const float* Wk   = (const float*)d_in[2];
    const float* Wv   = (const float*)d_in[3];
    const float* Wo   = (const float*)d_in[4];
    const float* bo   = (const float*)d_in[5];
    const float* ln1g = (const float*)d_in[6];
    const float* ln1b = (const float*)d_in[7];
    const float* ln2g = (const float*)d_in[8];
    const float* ln2b = (const float*)d_in[9];
    const float* W1   = (const float*)d_in[10];
    const float* b1   = (const float*)d_in[11];
    const float* W2   = (const float*)d_in[12];
    const float* b2   = (const float*)d_in[13];
    float* out = (float*)d_out;

    __half *a, *qh, *kh, *vh, *at, *ffh;
    float* x2;
    __half *wq, *wk, *wv, *wo, *w1, *w2;
    cudaGetSymbolAddress((void**)&a,   g_a);
    cudaGetSymbolAddress((void**)&qh,  g_qh);
    cudaGetSymbolAddress((void**)&kh,  g_kh);
    cudaGetSymbolAddress((void**)&vh,  g_vh);
    cudaGetSymbolAddress((void**)&at,  g_at);
    cudaGetSymbolAddress((void**)&ffh, g_ffh);
    cudaGetSymbolAddress((void**)&x2,  g_x2);
    cudaGetSymbolAddress((void**)&wq,  g_wq);
    cudaGetSymbolAddress((void**)&wk,  g_wk);
    cudaGetSymbolAddress((void**)&wv,  g_wv);
    cudaGetSymbolAddress((void**)&wo,  g_wo);
    cudaGetSymbolAddress((void**)&w1,  g_w1);
    cudaGetSymbolAddress((void**)&w2,  g_w2);

    cudaFuncSetAttribute(gemm_mma<0, 0>, cudaFuncAttributeMaxDynamicSharedMemorySize, GEMM_SMEM);
    cudaFuncSetAttribute(gemm_mma<0, 1>, cudaFuncAttributeMaxDynamicSharedMemorySize, GEMM_SMEM);
    cudaFuncSetAttribute(gemm_mma<1, 1>, cudaFuncAttributeMaxDynamicSharedMemorySize, GEMM_SMEM);

    dim3 wblk(32, 8);
    dim3 g1024(C_DIM / 128, M_ROWS / 128);
    dim3 g4096(FF_DIM / 128, M_ROWS / 128);

    // #1-#3: QKV weight transpose
    wtrans<<<dim3(C_DIM / 32, C_DIM / 32), wblk>>>(Wq, wq, C_DIM, C_DIM);
    wtrans<<<dim3(C_DIM / 32, C_DIM / 32), wblk>>>(Wk, wk, C_DIM, C_DIM);
    wtrans<<<dim3(C_DIM / 32, C_DIM / 32), wblk>>>(Wv, wv, C_DIM, C_DIM);
    // #4: ln1 -> fp16 activations
    ln_half<<<M_ROWS, 256>>>(x, ln1g, ln1b, a);
    // #5: Q projection (scaled by 1/8, fp16 out)
    gemm_mma<0, 1><<<g1024, 256, GEMM_SMEM>>>(a, wq, nullptr, nullptr,
                                              nullptr, qh, 0.125f, C_DIM, C_DIM);
    // #6: K projection  <-- ncu -s 5 -c 1 captures this
    gemm_mma<0, 1><<<g1024, 256, GEMM_SMEM>>>(a, wk, nullptr, nullptr,
                                              nullptr, kh, 1.0f, C_DIM, C_DIM);
    // #7: V projection
    gemm_mma<0, 1><<<g1024, 256, GEMM_SMEM>>>(a, wv, nullptr, nullptr,
                                              nullptr, vh, 1.0f, C_DIM, C_DIM);
    // #8-#10: remaining weight transposes
    wtrans<<<dim3(C_DIM / 32, C_DIM / 32), wblk>>>(Wo, wo, C_DIM, C_DIM);
    wtrans<<<dim3(FF_DIM / 32, C_DIM / 32), wblk>>>(W1, w1, C_DIM, FF_DIM);
    wtrans<<<dim3(C_DIM / 32, FF_DIM / 32), wblk>>>(W2, w2, FF_DIM, C_DIM);
    // #11: flash attention (fp16 tensor cores)
    attn_mma<<<dim3(T_SEQ / 64, H_NUM, B_NUM), 128>>>(qh, kh, vh, at);
    // #12: Wo projection + bias + residual -> x2 (fp32)
    gemm_mma<0, 0><<<g1024, 256, GEMM_SMEM>>>(at, wo, bo, x,
                                              x2, nullptr, 1.0f, C_DIM, C_DIM);
    // #13: ln2 -> fp16
    ln_half<<<M_ROWS, 256>>>(x2, ln2g, ln2b, a);
    // #14: MLP up + bias + ReLU (fp16 out)
    gemm_mma<1, 1><<<g4096, 256, GEMM_SMEM>>>(a, w1, b1, nullptr,
                                              nullptr, ffh, 1.0f, FF_DIM, C_DIM);
    // #15: MLP down + bias + residual -> out (fp32)
    gemm_mma<0, 0><<<g1024, 256, GEMM_SMEM>>>(ffh, w2, b2, x2,
                                              out, nullptr, 1.0f, C_DIM, FF_DIM);
}

// round 7
// speedup vs baseline: 3.6148x; 1.0310x over previous
#include <cuda_runtime.h>
#include <cuda_fp16.h>
#include <math.h>
#include <cstdint>

// ---------------------------------------------------------------------------
// MiniBlock: x + attn(ln1(x)); then + mlp(ln2(.))
// B=4, T=2048, C=1024, H=16, D=64, FF=4096.
// GEMMs: mma.sync fp16 single product. Fused QKV projection (N=3072).
// Attention: flash on mma.sync fp16, double-buffered K + register-staged V.
// ---------------------------------------------------------------------------

#define B_NUM 4
#define T_SEQ 2048
#define C_DIM 1024
#define H_NUM 16
#define D_HEAD 64
#define FF_DIM 4096
#define M_ROWS (B_NUM * T_SEQ)   // 8192
#define QKV_N (3 * C_DIM)        // 3072

// ---------------- scratch (device globals) ----------------------------------
__device__ __half g_a  [M_ROWS * C_DIM];    // ln output (fp16 activations)
__device__ __half g_qkv[M_ROWS * QKV_N];    // fused QKV output
__device__ __half g_at [M_ROWS * C_DIM];    // attention output
__device__ __half g_ffh[M_ROWS * FF_DIM];
__device__ float  g_x2 [M_ROWS * C_DIM];

__device__ __half g_wqkv[QKV_N * C_DIM];    // [3072,1024]: Wq^T | Wk^T | Wv^T
__device__ __half g_wo[C_DIM * C_DIM];
__device__ __half g_w1[FF_DIM * C_DIM];
__device__ __half g_w2[C_DIM * FF_DIM];

// ---------------- PTX helpers ------------------------------------------------
__device__ __forceinline__ uint32_t smem_u32(const void* p) {
    uint32_t a;
    asm("{ .reg .u64 t; cvta.to.shared.u64 t, %1; cvt.u32.u64 %0, t; }" : "=r"(a) : "l"(p));
    return a;
}
__device__ __forceinline__ void cp16(uint32_t dst, const void* src) {
    asm volatile("cp.async.cg.shared.global [%0], [%1], 16;" :: "r"(dst), "l"(src));
}
__device__ __forceinline__ void cp_commit() { asm volatile("cp.async.commit_group;" ::: "memory"); }
template <int N> __device__ __forceinline__ void cp_wait() {
    asm volatile("cp.async.wait_group %0;" :: "n"(N) : "memory");
}
__device__ __forceinline__ void ldsm4(uint32_t r[4], uint32_t addr) {
    asm volatile("ldmatrix.sync.aligned.m8n8.x4.shared.b16 {%0,%1,%2,%3}, [%4];"
                 : "=r"(r[0]), "=r"(r[1]), "=r"(r[2]), "=r"(r[3]) : "r"(addr));
}
__device__ __forceinline__ void mma_f16(float c[4], const uint32_t a[4],
                                        uint32_t b0, uint32_t b1) {
    asm volatile(
        "mma.sync.aligned.m16n8k16.row.col.f32.f16.f16.f32 "
        "{%0,%1,%2,%3}, {%4,%5,%6,%7}, {%8,%9}, {%0,%1,%2,%3};"
        : "+f"(c[0]), "+f"(c[1]), "+f"(c[2]), "+f"(c[3])
        : "r"(a[0]), "r"(a[1]), "r"(a[2]), "r"(a[3]), "r"(b0), "r"(b1));
}
__device__ __forceinline__ uint32_t packh2(float a, float b) {
    __half2 h = __floats2half2_rn(a, b);
    return *(uint32_t*)&h;
}

#define SWZ(x) ((x) ^ (((x) >> 3) & 0x70))

// ---------------------------------------------------------------------------
// fp16 GEMM: C[M,N] = A[M,K] @ B^T   (B stored [N,K] fp16)
// Block 128x128x64, 256 thr (8 warps 2x4), warp tile 64x32.
// 3-stage cp.async pipeline, 2 CTAs/SM.
// ---------------------------------------------------------------------------
static constexpr int GEMM_STAGE = 32768;           // A 16KB + B 16KB
static constexpr int GEMM_SMEM  = 3 * GEMM_STAGE;  // 98304

template <int RELU, int OUT_HALF>
__global__ __launch_bounds__(256, 2)
void gemm_mma(const __half* __restrict__ A, const __half* __restrict__ B,
              const float* __restrict__ bias, const float* __restrict__ res,
              float* __restrict__ Cf, __half* __restrict__ Oh,
              int N, int K) {
    extern __shared__ __align__(1024) char smem[];
    const uint32_t sb = smem_u32(smem);
    const int tid = threadIdx.x;
    const int lane = tid & 31;
    const int wid = tid >> 5;
    const int warp_m = wid >> 2;
    const int warp_n = wid & 3;
    const int n0 = blockIdx.x * 128;
    const int m0 = blockIdx.y * 128;
    const int nc = K >> 6;

    const int lrow = tid >> 1;
    const int lhalf = (tid & 1) * 64;
    const char* pa = (const char*)(A + (size_t)(m0 + lrow) * K) + lhalf;
    const char* pb = (const char*)(B + (size_t)(n0 + lrow) * K) + lhalf;

    auto issue = [&](int c) {
        uint32_t base = sb + (uint32_t)(c % 3) * GEMM_STAGE;
        size_t koff = (size_t)(c << 6) * 2;
#pragma unroll
        for (int j = 0; j < 4; j++) {
            uint32_t so = SWZ((uint32_t)(lrow * 128 + lhalf + j * 16));
            cp16(base + so,         pa + koff + j * 16);
            cp16(base + 16384 + so, pb + koff + j * 16);
        }
        cp_commit();
    };

    issue(0);
    if (nc > 1) issue(1);

    const int rowA = (lane & 7) + ((lane >> 3) & 1) * 8;
    const int colA = (lane >> 4) * 16;
    const int rowB = (lane & 7) + (lane >> 4) * 8;
    const int colB = ((lane >> 3) & 1) * 16;

    float acc[4][4][4];
#pragma unroll
    for (int a = 0; a < 4; a++)
#pragma unroll
        for (int b = 0; b < 4; b++)
#pragma unroll
            for (int r = 0; r < 4; r++) acc[a][b][r] = 0.f;

    for (int c = 0; c < nc; c++) {
        if (c + 1 < nc) cp_wait<1>(); else cp_wait<0>();
        __syncthreads();
        if (c + 2 < nc) issue(c + 2);

        uint32_t stb = sb + (uint32_t)(c % 3) * GEMM_STAGE;
#pragma unroll
        for (int ks = 0; ks < 4; ks++) {
            uint32_t ah[4][4], bh[2][4];
#pragma unroll
            for (int mt = 0; mt < 4; mt++) {
                uint32_t sw = SWZ((uint32_t)((warp_m * 64 + mt * 16 + rowA) * 128 + ks * 32 + colA));
                ldsm4(ah[mt], stb + sw);
            }
#pragma unroll
            for (int np = 0; np < 2; np++) {
                uint32_t sw = SWZ((uint32_t)((warp_n * 32 + np * 16 + rowB) * 128 + ks * 32 + colB));
                ldsm4(bh[np], stb + 16384 + sw);
            }
#pragma unroll
            for (int mt = 0; mt < 4; mt++)
#pragma unroll
                for (int nt = 0; nt < 4; nt++)
                    mma_f16(acc[mt][nt], ah[mt],
                            bh[nt >> 1][(nt & 1) * 2], bh[nt >> 1][(nt & 1) * 2 + 1]);
        }
    }

    const int rbase = m0 + warp_m * 64 + (lane >> 2);
    const int cbase = n0 + warp_n * 32 + (lane & 3) * 2;
#pragma unroll
    for (int mt = 0; mt < 4; mt++) {
#pragma unroll
        for (int nt = 0; nt < 4; nt++) {
            int col = cbase + nt * 8;
#pragma unroll
            for (int half = 0; half < 2; half++) {
                int row = rbase + mt * 16 + half * 8;
                float v0 = acc[mt][nt][half * 2 + 0];
                float v1 = acc[mt][nt][half * 2 + 1];
                if (bias) {
                    float2 b2 = *(const float2*)(bias + col);
                    v0 += b2.x; v1 += b2.y;
                }
                if (res) {
                    float2 r2 = *(const float2*)(res + (size_t)row * N + col);
                    v0 += r2.x; v1 += r2.y;
                }
                if (RELU) { v0 = fmaxf(v0, 0.f); v1 = fmaxf(v1, 0.f); }
                if (OUT_HALF) {
                    __half2 h = __floats2half2_rn(v0, v1);
                    *(__half2*)(Oh + (size_t)row * N + col) = h;
                } else {
                    float2 o2; o2.x = v0; o2.y = v1;
                    *(float2*)(Cf + (size_t)row * N + col) = o2;
                }
            }
        }
    }
}

// ---------------------------------------------------------------------------
// LayerNorm -> fp16 output. One block per row, 256 threads.
// ---------------------------------------------------------------------------
__global__ void ln_half(const float* __restrict__ x, const float* __restrict__ g,
                        const float* __restrict__ b, __half* __restrict__ o) {
    int row = blockIdx.x;
    int tid = threadIdx.x;
    const float4* xr = (const float4*)(x + (size_t)row * C_DIM);
    float4 v = xr[tid];
    float s = v.x + v.y + v.z + v.w;
    float q = v.x * v.x + v.y * v.y + v.z * v.z + v.w * v.w;
#pragma unroll
    for (int of = 16; of > 0; of >>= 1) {
        s += __shfl_xor_sync(0xffffffffu, s, of);
        q += __shfl_xor_sync(0xffffffffu, q, of);
    }
    __shared__ float ss[8], qs[8];
    if ((tid & 31) == 0) { ss[tid >> 5] = s; qs[tid >> 5] = q; }
    __syncthreads();
    float ts = 0.f, tq = 0.f;
#pragma unroll
    for (int i = 0; i < 8; i++) { ts += ss[i]; tq += qs[i]; }
    float mu = ts * (1.0f / C_DIM);
    float var = tq * (1.0f / C_DIM) - mu * mu;
    float rstd = rsqrtf(var + 1e-5f);
    float4 gg = ((const float4*)g)[tid];
    float4 bb = ((const float4*)b)[tid];
    float o0 = (v.x - mu) * rstd * gg.x + bb.x;
    float o1 = (v.y - mu) * rstd * gg.y + bb.y;
    float o2 = (v.z - mu) * rstd * gg.z + bb.z;
    float o3 = (v.w - mu) * rstd * gg.w + bb.w;
    __half2* po = (__half2*)(o + (size_t)row * C_DIM);
    po[tid * 2]     = __floats2half2_rn(o0, o1);
    po[tid * 2 + 1] = __floats2half2_rn(o2, o3);
}

// weight transpose (+scale): W[K,N] -> T[N,K] fp16
__global__ void wtrans(const float* __restrict__ W, __half* __restrict__ T,
                       int K, int N, float scale) {
    __shared__ float t[32][33];
    int n0 = blockIdx.x * 32, k0 = blockIdx.y * 32;
    int tx = threadIdx.x, ty = threadIdx.y;  // 32x8
#pragma unroll
    for (int i = 0; i < 32; i += 8) t[ty + i][tx] = W[(size_t)(k0 + ty + i) * N + n0 + tx];
    __syncthreads();
#pragma unroll
    for (int i = 0; i < 32; i += 8) {
        size_t o = (size_t)(n0 + ty + i) * K + k0 + tx;
        T[o] = __float2half_rn(t[tx][ty + i] * scale);
    }
}

// ---------------------------------------------------------------------------
// Flash attention on mma.sync fp16, reading fused QKV [M, 3072].
// Block = 4 warps, 64 q-rows. Double-buffered K smem; V staged in registers
// and transposed into double-buffered smem. K/V for kt+1 prefetched under
// the compute of kt. Q pre-scaled by 1/8 (in the weights). Output fp16.
// ---------------------------------------------------------------------------
struct ASmem {
    __half Qs[64 * 64];
    __half Ks[2][64 * 64];
    __half Vt[2][64 * 64];
};

__global__ __launch_bounds__(128, 3)
void attn_mma(const __half* __restrict__ QKV, __half* __restrict__ Og) {
    __shared__ ASmem s;
    const int qtx = blockIdx.x;
    const int NT = T_SEQ / 64;  // 32
    const int qt = (qtx & 1) ? (NT - 1 - (qtx >> 1)) : (qtx >> 1);  // balance
    const int h = blockIdx.y, b = blockIdx.z;
    const int tid = threadIdx.x;
    const int lane = tid & 31;
    const int w = tid >> 5;

    const __half* Qg = QKV + h * D_HEAD;
    const __half* Kg = QKV + C_DIM + h * D_HEAD;
    const __half* Vg = QKV + 2 * C_DIM + h * D_HEAD;

    const uint32_t sq = smem_u32(s.Qs);

    const int rowA = (lane & 7) + ((lane >> 3) & 1) * 8;
    const int colA = (lane >> 4) * 16;
    const int rowB = (lane & 7) + (lane >> 4) * 8;
    const int colB = ((lane >> 3) & 1) * 16;

    // Q tile load (cp.async)
    const int ldr = tid >> 1, ldh = (tid & 1) * 64;
    {
        const char* src = (const char*)(Qg + ((size_t)(b * T_SEQ + qt * 64 + ldr)) * QKV_N) + ldh;
#pragma unroll
        for (int j = 0; j < 4; j++)
            cp16(sq + SWZ((uint32_t)(ldr * 128 + ldh + j * 16)), src + j * 16);
        cp_commit();
    }
    cp_wait<0>();
    __syncthreads();

    uint32_t qa[4][4];
#pragma unroll
    for (int ks = 0; ks < 4; ks++)
        ldsm4(qa[ks], sq + SWZ((uint32_t)((w * 16 + rowA) * 128 + ks * 32 + colA)));

    // prefetch K[0] + V[0]
    const int vkp = (lane) * 2;          // kpos pair
    const int vd0 = w * 16;              // 16 d values
    __half va0[16], va1[16];
    auto issueK = [&](int kt, int buf) {
        const uint32_t skb = smem_u32(s.Ks[buf]);
        const char* src = (const char*)(Kg + ((size_t)(b * T_SEQ + kt * 64 + ldr)) * QKV_N) + ldh;
#pragma unroll
        for (int j = 0; j < 4; j++)
            cp16(skb + SWZ((uint32_t)(ldr * 128 + ldh + j * 16)), src + j * 16);
        cp_commit();
    };
    auto loadV = [&](int kt) {
        const uint4* p0 = (const uint4*)(Vg + ((size_t)(b * T_SEQ + kt * 64 + vkp)) * QKV_N + vd0);
        const uint4* p1 = (const uint4*)(Vg + ((size_t)(b * T_SEQ + kt * 64 + vkp + 1)) * QKV_N + vd0);
        *(uint4*)(va0) = p0[0]; *(uint4*)(va0 + 8) = p0[1];
        *(uint4*)(va1) = p1[0]; *(uint4*)(va1 + 8) = p1[1];
    };
    issueK(0, 0);
    loadV(0);

    float m0 = -1e30f, m1 = -1e30f, l0 = 0.f, l1 = 0.f;
    float oacc[8][4];
#pragma unroll
    for (int nt = 0; nt < 8; nt++)
#pragma unroll
        for (int r = 0; r < 4; r++) oacc[nt][r] = 0.f;

    for (int kt = 0; kt <= qt; kt++) {
        const int buf = kt & 1;
        cp_wait<0>();  // K[kt] resident
        // stage V regs into Vt[buf] (last readers of Vt[buf] were kt-2, behind kt-1's sync)
        {
            char* svp = (char*)s.Vt[buf];
#pragma unroll
            for (int i = 0; i < 16; i++) {
                int d = vd0 + i;
                *(__half2*)(svp + SWZ((uint32_t)(d * 128 + vkp * 2))) = __halves2half2(va0[i], va1[i]);
            }
        }
        __syncthreads();  // K[buf] + Vt[buf] visible to all warps

        // prefetch next tile under this tile's compute
        if (kt < qt) {
            issueK(kt + 1, buf ^ 1);
            loadV(kt + 1);
        }

        const uint32_t sk = smem_u32(s.Ks[buf]);
        const uint32_t sv = smem_u32(s.Vt[buf]);

        // S = Q @ K^T
        float sacc[8][4];
#pragma unroll
        for (int nt = 0; nt < 8; nt++)
#pragma unroll
            for (int r = 0; r < 4; r++) sacc[nt][r] = 0.f;
#pragma unroll
        for (int ks = 0; ks < 4; ks++) {
            uint32_t kb[4][4];
#pragma unroll
            for (int p = 0; p < 4; p++)
                ldsm4(kb[p], sk + SWZ((uint32_t)((p * 16 + rowB) * 128 + ks * 32 + colB)));
#pragma unroll
            for (int nt = 0; nt < 8; nt++)
                mma_f16(sacc[nt], qa[ks], kb[nt >> 1][(nt & 1) * 2], kb[nt >> 1][(nt & 1) * 2 + 1]);
        }

        if (kt == qt) {
            int rl0 = w * 16 + (lane >> 2);
            int rl1 = rl0 + 8;
#pragma unroll
            for (int nt = 0; nt < 8; nt++) {
                int cl = nt * 8 + 2 * (lane & 3);
                if (cl > rl0)     sacc[nt][0] = -1e30f;
                if (cl + 1 > rl0) sacc[nt][1] = -1e30f;
                if (cl > rl1)     sacc[nt][2] = -1e30f;
                if (cl + 1 > rl1) sacc[nt][3] = -1e30f;
            }
        }

        float mx0 = -1e30f, mx1 = -1e30f;
#pragma unroll
        for (int nt = 0; nt < 8; nt++) {
            mx0 = fmaxf(mx0, fmaxf(sacc[nt][0], sacc[nt][1]));
            mx1 = fmaxf(mx1, fmaxf(sacc[nt][2], sacc[nt][3]));
        }
        mx0 = fmaxf(mx0, __shfl_xor_sync(0xffffffffu, mx0, 1));
        mx0 = fmaxf(mx0, __shfl_xor_sync(0xffffffffu, mx0, 2));
        mx1 = fmaxf(mx1, __shfl_xor_sync(0xffffffffu, mx1, 1));
        mx1 = fmaxf(mx1, __shfl_xor_sync(0xffffffffu, mx1, 2));
        float mn0 = fmaxf(m0, mx0), mn1 = fmaxf(m1, mx1);
        float al0 = __expf(m0 - mn0), al1 = __expf(m1 - mn1);
        m0 = mn0; m1 = mn1;

        float s0 = 0.f, s1 = 0.f;
#pragma unroll
        for (int nt = 0; nt < 8; nt++) {
            sacc[nt][0] = __expf(sacc[nt][0] - mn0);
            sacc[nt][1] = __expf(sacc[nt][1] - mn0);
            sacc[nt][2] = __expf(sacc[nt][2] - mn1);
            sacc[nt][3] = __expf(sacc[nt][3] - mn1);
            s0 += sacc[nt][0] + sacc[nt][1];
            s1 += sacc[nt][2] + sacc[nt][3];
        }
        s0 += __shfl_xor_sync(0xffffffffu, s0, 1);
        s0 += __shfl_xor_sync(0xffffffffu, s0, 2);
        s1 += __shfl_xor_sync(0xffffffffu, s1, 1);
        s1 += __shfl_xor_sync(0xffffffffu, s1, 2);
        l0 = l0 * al0 + s0;
        l1 = l1 * al1 + s1;

#pragma unroll
        for (int nt = 0; nt < 8; nt++) {
            oacc[nt][0] *= al0; oacc[nt][1] *= al0;
            oacc[nt][2] *= al1; oacc[nt][3] *= al1;
        }

        uint32_t pa[4][4];
#pragma unroll
        for (int ks = 0; ks < 4; ks++) {
            pa[ks][0] = packh2(sacc[2 * ks][0], sacc[2 * ks][1]);
            pa[ks][1] = packh2(sacc[2 * ks][2], sacc[2 * ks][3]);
            pa[ks][2] = packh2(sacc[2 * ks + 1][0], sacc[2 * ks + 1][1]);
            pa[ks][3] = packh2(sacc[2 * ks + 1][2], sacc[2 * ks + 1][3]);
        }

#pragma unroll
        for (int ks = 0; ks < 4; ks++) {
            uint32_t vb[4][4];
#pragma unroll
            for (int p = 0; p < 4; p++)
                ldsm4(vb[p], sv + SWZ((uint32_t)((p * 16 + rowB) * 128 + ks * 32 + colB)));
#pragma unroll
            for (int nt = 0; nt < 8; nt++)
                mma_f16(oacc[nt], pa[ks], vb[nt >> 1][(nt & 1) * 2], vb[nt >> 1][(nt & 1) * 2 + 1]);
        }
    }

    float inv0 = 1.0f / l0, inv1 = 1.0f / l1;
    int row0 = qt * 64 + w * 16 + (lane >> 2);
    int row1 = row0 + 8;
#pragma unroll
    for (int nt = 0; nt < 8; nt++) {
        int col = h * D_HEAD + nt * 8 + 2 * (lane & 3);
        *(__half2*)(Og + ((size_t)(b * T_SEQ + row0)) * C_DIM + col) =
            __floats2half2_rn(oacc[nt][0] * inv0, oacc[nt][1] * inv0);
        *(__half2*)(Og + ((size_t)(b * T_SEQ + row1)) * C_DIM + col) =
            __floats2half2_rn(oacc[nt][2] * inv1, oacc[nt][3] * inv1);
    }
}

// ---------------------------------------------------------------------------
// Launch
// ---------------------------------------------------------------------------
extern "C" void kernel_launch(void* const* d_in, const int* in_sizes, int n_in,
                              void* d_out, int out_size) {
    const float* x    = (const float*)d_in[0];
    const float* Wq   = (const float*)d_in[1];
    const float* Wk   = (const float*)d_in[2];
    const float* Wv   = (const float*)d_in[3];
    const float* Wo   = (const float*)d_in[4];
    const float* bo   = (const float*)d_in[5];
    const float* ln1g = (const float*)d_in[6];
    const float* ln1b = (const float*)d_in[7];
    const float* ln2g = (const float*)d_in[8];
    const float* ln2b = (const float*)d_in[9];
    const float* W1   = (const float*)d_in[10];
    const float* b1   = (const float*)d_in[11];
    const float* W2   = (const float*)d_in[12];
    const float* b2   = (const float*)d_in[13];
    float* out = (float*)d_out;

    __half *a, *qkv, *at, *ffh;
    float* x2;
    __half *wqkv, *wo, *w1, *w2;
    cudaGetSymbolAddress((void**)&a,    g_a);
    cudaGetSymbolAddress((void**)&qkv,  g_qkv);
    cudaGetSymbolAddress((void**)&at,   g_at);
    cudaGetSymbolAddress((void**)&ffh,  g_ffh);
    cudaGetSymbolAddress((void**)&x2,   g_x2);
    cudaGetSymbolAddress((void**)&wqkv, g_wqkv);
    cudaGetSymbolAddress((void**)&wo,   g_wo);
    cudaGetSymbolAddress((void**)&w1,   g_w1);
    cudaGetSymbolAddress((void**)&w2,   g_w2);

    cudaFuncSetAttribute(gemm_mma<0, 0>, cudaFuncAttributeMaxDynamicSharedMemorySize, GEMM_SMEM);
    cudaFuncSetAttribute(gemm_mma<0, 1>, cudaFuncAttributeMaxDynamicSharedMemorySize, GEMM_SMEM);
    cudaFuncSetAttribute(gemm_mma<1, 1>, cudaFuncAttributeMaxDynamicSharedMemorySize, GEMM_SMEM);

    dim3 wblk(32, 8);
    dim3 gQKV(QKV_N / 128, M_ROWS / 128);   // (24, 64)
    dim3 g1024(C_DIM / 128, M_ROWS / 128);  // (8, 64)
    dim3 g4096(FF_DIM / 128, M_ROWS / 128); // (32, 64)

    // QKV weight transposes into the fused [3072,1024] buffer.
    // Wq pre-scaled by 1/8 (exact power of two, identical rounding).
    wtrans<<<dim3(C_DIM / 32, C_DIM / 32), wblk>>>(Wq, wqkv,                 C_DIM, C_DIM, 0.125f);
    wtrans<<<dim3(C_DIM / 32, C_DIM / 32), wblk>>>(Wk, wqkv + C_DIM * C_DIM, C_DIM, C_DIM, 1.0f);
    wtrans<<<dim3(C_DIM / 32, C_DIM / 32), wblk>>>(Wv, wqkv + 2 * C_DIM * C_DIM, C_DIM, C_DIM, 1.0f);
    // ln1 -> fp16 activations
    ln_half<<<M_ROWS, 256>>>(x, ln1g, ln1b, a);
    // fused QKV projection (fp16 out)
    gemm_mma<0, 1><<<gQKV, 256, GEMM_SMEM>>>(a, wqkv, nullptr, nullptr,
                                             nullptr, qkv, QKV_N, C_DIM);
    // remaining weight transposes
    wtrans<<<dim3(C_DIM / 32, C_DIM / 32), wblk>>>(Wo, wo, C_DIM, C_DIM, 1.0f);
    wtrans<<<dim3(FF_DIM / 32, C_DIM / 32), wblk>>>(W1, w1, C_DIM, FF_DIM, 1.0f);
    wtrans<<<dim3(C_DIM / 32, FF_DIM / 32), wblk>>>(W2, w2, FF_DIM, C_DIM, 1.0f);
    // flash attention (fp16 tensor cores)
    attn_mma<<<dim3(T_SEQ / 64, H_NUM, B_NUM), 128>>>(qkv, at);
    // Wo projection + bias + residual -> x2 (fp32)
    gemm_mma<0, 0><<<g1024, 256, GEMM_SMEM>>>(at, wo, bo, x,
                                              x2, nullptr, C_DIM, C_DIM);
    // ln2 -> fp16
    ln_half<<<M_ROWS, 256>>>(x2, ln2g, ln2b, a);
    // MLP up + bias + ReLU (fp16 out)
    gemm_mma<1, 1><<<g4096, 256, GEMM_SMEM>>>(a, w1, b1, nullptr,
                                              nullptr, ffh, FF_DIM, C_DIM);
    // MLP down + bias + residual -> out (fp32)
    gemm_mma<0, 0><<<g1024, 256, GEMM_SMEM>>>(ffh, w2, b2, x2,
                                              out, nullptr, C_DIM, FF_DIM);
}

// round 8
// speedup vs baseline: 3.6346x; 1.0055x over previous
#include <cuda_runtime.h>
#include <cuda_fp16.h>
#include <math.h>
#include <cstdint>

// ---------------------------------------------------------------------------
// MiniBlock: x + attn(ln1(x)); then + mlp(ln2(.))
// B=4, T=2048, C=1024, H=16, D=64, FF=4096.
// GEMMs: mma.sync fp16 single product (issue-rate floor ~780us).
// Attention: flash, 128-row q-tiles, 8 warps, exp2 softmax, double-buffered K/V.
// ---------------------------------------------------------------------------

#define B_NUM 4
#define T_SEQ 2048
#define C_DIM 1024
#define H_NUM 16
#define D_HEAD 64
#define FF_DIM 4096
#define M_ROWS (B_NUM * T_SEQ)   // 8192
#define QKV_N (3 * C_DIM)        // 3072

// ---------------- scratch (device globals) ----------------------------------
__device__ __half g_a  [M_ROWS * C_DIM];
__device__ __half g_qkv[M_ROWS * QKV_N];
__device__ __half g_at [M_ROWS * C_DIM];
__device__ __half g_ffh[M_ROWS * FF_DIM];
__device__ float  g_x2 [M_ROWS * C_DIM];

__device__ __half g_wqkv[QKV_N * C_DIM];
__device__ __half g_wo[C_DIM * C_DIM];
__device__ __half g_w1[FF_DIM * C_DIM];
__device__ __half g_w2[C_DIM * FF_DIM];

// ---------------- PTX helpers ------------------------------------------------
__device__ __forceinline__ uint32_t smem_u32(const void* p) {
    uint32_t a;
    asm("{ .reg .u64 t; cvta.to.shared.u64 t, %1; cvt.u32.u64 %0, t; }" : "=r"(a) : "l"(p));
    return a;
}
__device__ __forceinline__ void cp16(uint32_t dst, const void* src) {
    asm volatile("cp.async.cg.shared.global [%0], [%1], 16;" :: "r"(dst), "l"(src));
}
__device__ __forceinline__ void cp_commit() { asm volatile("cp.async.commit_group;" ::: "memory"); }
template <int N> __device__ __forceinline__ void cp_wait() {
    asm volatile("cp.async.wait_group %0;" :: "n"(N) : "memory");
}
__device__ __forceinline__ void ldsm4(uint32_t r[4], uint32_t addr) {
    asm volatile("ldmatrix.sync.aligned.m8n8.x4.shared.b16 {%0,%1,%2,%3}, [%4];"
                 : "=r"(r[0]), "=r"(r[1]), "=r"(r[2]), "=r"(r[3]) : "r"(addr));
}
__device__ __forceinline__ void mma_f16(float c[4], const uint32_t a[4],
                                        uint32_t b0, uint32_t b1) {
    asm volatile(
        "mma.sync.aligned.m16n8k16.row.col.f32.f16.f16.f32 "
        "{%0,%1,%2,%3}, {%4,%5,%6,%7}, {%8,%9}, {%0,%1,%2,%3};"
        : "+f"(c[0]), "+f"(c[1]), "+f"(c[2]), "+f"(c[3])
        : "r"(a[0]), "r"(a[1]), "r"(a[2]), "r"(a[3]), "r"(b0), "r"(b1));
}
__device__ __forceinline__ uint32_t packh2(float a, float b) {
    __half2 h = __floats2half2_rn(a, b);
    return *(uint32_t*)&h;
}
__device__ __forceinline__ float ex2(float x) {
    float y;
    asm("ex2.approx.f32 %0, %1;" : "=f"(y) : "f"(x));
    return y;
}

#define SWZ(x) ((x) ^ (((x) >> 3) & 0x70))

// ---------------------------------------------------------------------------
// fp16 GEMM: C[M,N] = A[M,K] @ B^T   (B stored [N,K] fp16)
// Block 128x128x64, 256 thr (8 warps 2x4), warp tile 64x32.
// 3-stage cp.async pipeline, 2 CTAs/SM.  (At the mma.sync issue floor.)
// ---------------------------------------------------------------------------
static constexpr int GEMM_STAGE = 32768;
static constexpr int GEMM_SMEM  = 3 * GEMM_STAGE;  // 98304

template <int RELU, int OUT_HALF>
__global__ __launch_bounds__(256, 2)
void gemm_mma(const __half* __restrict__ A, const __half* __restrict__ B,
              const float* __restrict__ bias, const float* __restrict__ res,
              float* __restrict__ Cf, __half* __restrict__ Oh,
              int N, int K) {
    extern __shared__ __align__(1024) char smem[];
    const uint32_t sb = smem_u32(smem);
    const int tid = threadIdx.x;
    const int lane = tid & 31;
    const int wid = tid >> 5;
    const int warp_m = wid >> 2;
    const int warp_n = wid & 3;
    const int n0 = blockIdx.x * 128;
    const int m0 = blockIdx.y * 128;
    const int nc = K >> 6;

    const int lrow = tid >> 1;
    const int lhalf = (tid & 1) * 64;
    const char* pa = (const char*)(A + (size_t)(m0 + lrow) * K) + lhalf;
    const char* pb = (const char*)(B + (size_t)(n0 + lrow) * K) + lhalf;

    auto issue = [&](int c) {
        uint32_t base = sb + (uint32_t)(c % 3) * GEMM_STAGE;
        size_t koff = (size_t)(c << 6) * 2;
#pragma unroll
        for (int j = 0; j < 4; j++) {
            uint32_t so = SWZ((uint32_t)(lrow * 128 + lhalf + j * 16));
            cp16(base + so,         pa + koff + j * 16);
            cp16(base + 16384 + so, pb + koff + j * 16);
        }
        cp_commit();
    };

    issue(0);
    if (nc > 1) issue(1);

    const int rowA = (lane & 7) + ((lane >> 3) & 1) * 8;
    const int colA = (lane >> 4) * 16;
    const int rowB = (lane & 7) + (lane >> 4) * 8;
    const int colB = ((lane >> 3) & 1) * 16;

    float acc[4][4][4];
#pragma unroll
    for (int a = 0; a < 4; a++)
#pragma unroll
        for (int b = 0; b < 4; b++)
#pragma unroll
            for (int r = 0; r < 4; r++) acc[a][b][r] = 0.f;

    for (int c = 0; c < nc; c++) {
        if (c + 1 < nc) cp_wait<1>(); else cp_wait<0>();
        __syncthreads();
        if (c + 2 < nc) issue(c + 2);

        uint32_t stb = sb + (uint32_t)(c % 3) * GEMM_STAGE;
#pragma unroll
        for (int ks = 0; ks < 4; ks++) {
            uint32_t ah[4][4], bh[2][4];
#pragma unroll
            for (int mt = 0; mt < 4; mt++) {
                uint32_t sw = SWZ((uint32_t)((warp_m * 64 + mt * 16 + rowA) * 128 + ks * 32 + colA));
                ldsm4(ah[mt], stb + sw);
            }
#pragma unroll
            for (int np = 0; np < 2; np++) {
                uint32_t sw = SWZ((uint32_t)((warp_n * 32 + np * 16 + rowB) * 128 + ks * 32 + colB));
                ldsm4(bh[np], stb + 16384 + sw);
            }
#pragma unroll
            for (int mt = 0; mt < 4; mt++)
#pragma unroll
                for (int nt = 0; nt < 4; nt++)
                    mma_f16(acc[mt][nt], ah[mt],
                            bh[nt >> 1][(nt & 1) * 2], bh[nt >> 1][(nt & 1) * 2 + 1]);
        }
    }

    const int rbase = m0 + warp_m * 64 + (lane >> 2);
    const int cbase = n0 + warp_n * 32 + (lane & 3) * 2;
#pragma unroll
    for (int mt = 0; mt < 4; mt++) {
#pragma unroll
        for (int nt = 0; nt < 4; nt++) {
            int col = cbase + nt * 8;
#pragma unroll
            for (int half = 0; half < 2; half++) {
                int row = rbase + mt * 16 + half * 8;
                float v0 = acc[mt][nt][half * 2 + 0];
                float v1 = acc[mt][nt][half * 2 + 1];
                if (bias) {
                    float2 b2 = *(const float2*)(bias + col);
                    v0 += b2.x; v1 += b2.y;
                }
                if (res) {
                    float2 r2 = *(const float2*)(res + (size_t)row * N + col);
                    v0 += r2.x; v1 += r2.y;
                }
                if (RELU) { v0 = fmaxf(v0, 0.f); v1 = fmaxf(v1, 0.f); }
                if (OUT_HALF) {
                    __half2 h = __floats2half2_rn(v0, v1);
                    *(__half2*)(Oh + (size_t)row * N + col) = h;
                } else {
                    float2 o2; o2.x = v0; o2.y = v1;
                    *(float2*)(Cf + (size_t)row * N + col) = o2;
                }
            }
        }
    }
}

// ---------------------------------------------------------------------------
// LayerNorm -> fp16 output. One block per row, 256 threads.
// ---------------------------------------------------------------------------
__global__ void ln_half(const float* __restrict__ x, const float* __restrict__ g,
                        const float* __restrict__ b, __half* __restrict__ o) {
    int row = blockIdx.x;
    int tid = threadIdx.x;
    const float4* xr = (const float4*)(x + (size_t)row * C_DIM);
    float4 v = xr[tid];
    float s = v.x + v.y + v.z + v.w;
    float q = v.x * v.x + v.y * v.y + v.z * v.z + v.w * v.w;
#pragma unroll
    for (int of = 16; of > 0; of >>= 1) {
        s += __shfl_xor_sync(0xffffffffu, s, of);
        q += __shfl_xor_sync(0xffffffffu, q, of);
    }
    __shared__ float ss[8], qs[8];
    if ((tid & 31) == 0) { ss[tid >> 5] = s; qs[tid >> 5] = q; }
    __syncthreads();
    float ts = 0.f, tq = 0.f;
#pragma unroll
    for (int i = 0; i < 8; i++) { ts += ss[i]; tq += qs[i]; }
    float mu = ts * (1.0f / C_DIM);
    float var = tq * (1.0f / C_DIM) - mu * mu;
    float rstd = rsqrtf(var + 1e-5f);
    float4 gg = ((const float4*)g)[tid];
    float4 bb = ((const float4*)b)[tid];
    float o0 = (v.x - mu) * rstd * gg.x + bb.x;
    float o1 = (v.y - mu) * rstd * gg.y + bb.y;
    float o2 = (v.z - mu) * rstd * gg.z + bb.z;
    float o3 = (v.w - mu) * rstd * gg.w + bb.w;
    __half2* po = (__half2*)(o + (size_t)row * C_DIM);
    po[tid * 2]     = __floats2half2_rn(o0, o1);
    po[tid * 2 + 1] = __floats2half2_rn(o2, o3);
}

// ---------------------------------------------------------------------------
// Batched weight transpose (+scale): all 6 weights in ONE launch.
// W[K,N] -> T[N,K] fp16. Tiles mapped by linear blockIdx.x.
// ---------------------------------------------------------------------------
struct WJobs {
    const float* src[6];
    __half* dst[6];
    int K[6], N[6], start[7];
    float scale[6];
};

__global__ void wtrans_all(WJobs jobs) {
    __shared__ float t[32][33];
    int bx = blockIdx.x;
    int j = 0;
#pragma unroll
    for (int i = 1; i < 6; i++)
        if (bx >= jobs.start[i]) j = i;
    int idx = bx - jobs.start[j];
    int K = jobs.K[j], N = jobs.N[j];
    int ntiles = N >> 5;
    int n0 = (idx % ntiles) * 32;
    int k0 = (idx / ntiles) * 32;
    const float* W = jobs.src[j];
    __half* T = jobs.dst[j];
    float scale = jobs.scale[j];
    int tx = threadIdx.x, ty = threadIdx.y;  // 32x8
#pragma unroll
    for (int i = 0; i < 32; i += 8) t[ty + i][tx] = W[(size_t)(k0 + ty + i) * N + n0 + tx];
    __syncthreads();
#pragma unroll
    for (int i = 0; i < 32; i += 8) {
        size_t o = (size_t)(n0 + ty + i) * K + k0 + tx;
        T[o] = __float2half_rn(t[tx][ty + i] * scale);
    }
}

// ---------------------------------------------------------------------------
// Flash attention on mma.sync fp16, fused QKV input [M, 3072].
// 128-row q-tiles, 8 warps (256 thr), 2 CTAs/SM. K tiles of 64, double
// buffered; V staged via registers into transposed smem. exp2 softmax
// (log2e folded into Wq). Output fp16.
// ---------------------------------------------------------------------------
struct ASmem {
    __half Qs[128 * 64];     // 16 KB
    __half Ks[2][64 * 64];   // 16 KB
    __half Vt[2][64 * 64];   // 16 KB
};

__global__ __launch_bounds__(256, 2)
void attn_mma(const __half* __restrict__ QKV, __half* __restrict__ Og) {
    __shared__ ASmem s;
    const int qtx = blockIdx.x;
    const int NT = T_SEQ / 128;  // 16
    const int qt = (qtx & 1) ? (NT - 1 - (qtx >> 1)) : (qtx >> 1);  // balance
    const int h = blockIdx.y, b = blockIdx.z;
    const int tid = threadIdx.x;
    const int lane = tid & 31;
    const int w = tid >> 5;      // 0..7

    const __half* Qg = QKV + h * D_HEAD;
    const __half* Kg = QKV + C_DIM + h * D_HEAD;
    const __half* Vg = QKV + 2 * C_DIM + h * D_HEAD;

    const uint32_t sq = smem_u32(s.Qs);

    const int rowA = (lane & 7) + ((lane >> 3) & 1) * 8;
    const int colA = (lane >> 4) * 16;
    const int rowB = (lane & 7) + (lane >> 4) * 8;
    const int colB = ((lane >> 3) & 1) * 16;

    // Q tile load: 128 rows x 128B, 256 threads x 4 cp16
    {
        int r = tid >> 1, hh = (tid & 1) * 64;
        const char* src = (const char*)(Qg + ((size_t)(b * T_SEQ + qt * 128 + r)) * QKV_N) + hh;
#pragma unroll
        for (int j = 0; j < 4; j++)
            cp16(sq + SWZ((uint32_t)(r * 128 + hh + j * 16)), src + j * 16);
        cp_commit();
    }
    cp_wait<0>();
    __syncthreads();

    uint32_t qa[4][4];
#pragma unroll
    for (int ks = 0; ks < 4; ks++)
        ldsm4(qa[ks], sq + SWZ((uint32_t)((w * 16 + rowA) * 128 + ks * 32 + colA)));

    // K: 64 rows x 128B, 256 threads x 2 cp16
    const int kr = tid >> 2, kq = (tid & 3) * 32;
    auto issueK = [&](int kt, int buf) {
        const uint32_t skb = smem_u32(s.Ks[buf]);
        const char* src = (const char*)(Kg + ((size_t)(b * T_SEQ + kt * 64 + kr)) * QKV_N) + kq;
#pragma unroll
        for (int j = 0; j < 2; j++)
            cp16(skb + SWZ((uint32_t)(kr * 128 + kq + j * 16)), src + j * 16);
        cp_commit();
    };
    // V: thread stages kpos pair (vkp, vkp+1) x 8 d values
    const int vkp = lane * 2;
    const int vd0 = w * 8;
    __half va0[8], va1[8];
    auto loadV = [&](int kt) {
        const uint4* p0 = (const uint4*)(Vg + ((size_t)(b * T_SEQ + kt * 64 + vkp)) * QKV_N + vd0);
        const uint4* p1 = (const uint4*)(Vg + ((size_t)(b * T_SEQ + kt * 64 + vkp + 1)) * QKV_N + vd0);
        *(uint4*)(va0) = p0[0];
        *(uint4*)(va1) = p1[0];
    };
    issueK(0, 0);
    loadV(0);

    float m0 = -1e30f, m1 = -1e30f, l0 = 0.f, l1 = 0.f;
    float oacc[8][4];
#pragma unroll
    for (int nt = 0; nt < 8; nt++)
#pragma unroll
        for (int r = 0; r < 4; r++) oacc[nt][r] = 0.f;

    const int nkt = 2 * qt + 2;
    for (int kt = 0; kt < nkt; kt++) {
        const int buf = kt & 1;
        cp_wait<0>();
        {
            char* svp = (char*)s.Vt[buf];
#pragma unroll
            for (int i = 0; i < 8; i++) {
                int d = vd0 + i;
                *(__half2*)(svp + SWZ((uint32_t)(d * 128 + vkp * 2))) = __halves2half2(va0[i], va1[i]);
            }
        }
        __syncthreads();

        if (kt + 1 < nkt) {
            issueK(kt + 1, buf ^ 1);
            loadV(kt + 1);
        }

        const uint32_t sk = smem_u32(s.Ks[buf]);
        const uint32_t sv = smem_u32(s.Vt[buf]);

        // S = Q @ K^T
        float sacc[8][4];
#pragma unroll
        for (int nt = 0; nt < 8; nt++)
#pragma unroll
            for (int r = 0; r < 4; r++) sacc[nt][r] = 0.f;
#pragma unroll
        for (int ks = 0; ks < 4; ks++) {
            uint32_t kb[4][4];
#pragma unroll
            for (int p = 0; p < 4; p++)
                ldsm4(kb[p], sk + SWZ((uint32_t)((p * 16 + rowB) * 128 + ks * 32 + colB)));
#pragma unroll
            for (int nt = 0; nt < 8; nt++)
                mma_f16(sacc[nt], qa[ks], kb[nt >> 1][(nt & 1) * 2], kb[nt >> 1][(nt & 1) * 2 + 1]);
        }

        // causal mask: only the two diagonal-crossing tiles need it
        if (kt >= 2 * qt) {
            int grow0 = qt * 128 + w * 16 + (lane >> 2);
            int grow1 = grow0 + 8;
            int gc0 = kt * 64 + 2 * (lane & 3);
#pragma unroll
            for (int nt = 0; nt < 8; nt++) {
                int cl = gc0 + nt * 8;
                if (cl > grow0)     sacc[nt][0] = -1e30f;
                if (cl + 1 > grow0) sacc[nt][1] = -1e30f;
                if (cl > grow1)     sacc[nt][2] = -1e30f;
                if (cl + 1 > grow1) sacc[nt][3] = -1e30f;
            }
        }

        float mx0 = -1e30f, mx1 = -1e30f;
#pragma unroll
        for (int nt = 0; nt < 8; nt++) {
            mx0 = fmaxf(mx0, fmaxf(sacc[nt][0], sacc[nt][1]));
            mx1 = fmaxf(mx1, fmaxf(sacc[nt][2], sacc[nt][3]));
        }
        mx0 = fmaxf(mx0, __shfl_xor_sync(0xffffffffu, mx0, 1));
        mx0 = fmaxf(mx0, __shfl_xor_sync(0xffffffffu, mx0, 2));
        mx1 = fmaxf(mx1, __shfl_xor_sync(0xffffffffu, mx1, 1));
        mx1 = fmaxf(mx1, __shfl_xor_sync(0xffffffffu, mx1, 2));
        float mn0 = fmaxf(m0, mx0), mn1 = fmaxf(m1, mx1);
        float al0 = ex2(m0 - mn0), al1 = ex2(m1 - mn1);
        m0 = mn0; m1 = mn1;

        float s0 = 0.f, s1 = 0.f;
#pragma unroll
        for (int nt = 0; nt < 8; nt++) {
            sacc[nt][0] = ex2(sacc[nt][0] - mn0);
            sacc[nt][1] = ex2(sacc[nt][1] - mn0);
            sacc[nt][2] = ex2(sacc[nt][2] - mn1);
            sacc[nt][3] = ex2(sacc[nt][3] - mn1);
            s0 += sacc[nt][0] + sacc[nt][1];
            s1 += sacc[nt][2] + sacc[nt][3];
        }
        s0 += __shfl_xor_sync(0xffffffffu, s0, 1);
        s0 += __shfl_xor_sync(0xffffffffu, s0, 2);
        s1 += __shfl_xor_sync(0xffffffffu, s1, 1);
        s1 += __shfl_xor_sync(0xffffffffu, s1, 2);
        l0 = l0 * al0 + s0;
        l1 = l1 * al1 + s1;

#pragma unroll
        for (int nt = 0; nt < 8; nt++) {
            oacc[nt][0] *= al0; oacc[nt][1] *= al0;
            oacc[nt][2] *= al1; oacc[nt][3] *= al1;
        }

        uint32_t pa[4][4];
#pragma unroll
        for (int ks = 0; ks < 4; ks++) {
            pa[ks][0] = packh2(sacc[2 * ks][0], sacc[2 * ks][1]);
            pa[ks][1] = packh2(sacc[2 * ks][2], sacc[2 * ks][3]);
            pa[ks][2] = packh2(sacc[2 * ks + 1][0], sacc[2 * ks + 1][1]);
            pa[ks][3] = packh2(sacc[2 * ks + 1][2], sacc[2 * ks + 1][3]);
        }

#pragma unroll
        for (int ks = 0; ks < 4; ks++) {
            uint32_t vb[4][4];
#pragma unroll
            for (int p = 0; p < 4; p++)
                ldsm4(vb[p], sv + SWZ((uint32_t)((p * 16 + rowB) * 128 + ks * 32 + colB)));
#pragma unroll
            for (int nt = 0; nt < 8; nt++)
                mma_f16(oacc[nt], pa[ks], vb[nt >> 1][(nt & 1) * 2], vb[nt >> 1][(nt & 1) * 2 + 1]);
        }
    }

    float inv0 = 1.0f / l0, inv1 = 1.0f / l1;
    int row0 = qt * 128 + w * 16 + (lane >> 2);
    int row1 = row0 + 8;
#pragma unroll
    for (int nt = 0; nt < 8; nt++) {
        int col = h * D_HEAD + nt * 8 + 2 * (lane & 3);
        *(__half2*)(Og + ((size_t)(b * T_SEQ + row0)) * C_DIM + col) =
            __floats2half2_rn(oacc[nt][0] * inv0, oacc[nt][1] * inv0);
        *(__half2*)(Og + ((size_t)(b * T_SEQ + row1)) * C_DIM + col) =
            __floats2half2_rn(oacc[nt][2] * inv1, oacc[nt][3] * inv1);
    }
}

// ---------------------------------------------------------------------------
// Launch
// ---------------------------------------------------------------------------
extern "C" void kernel_launch(void* const* d_in, const int* in_sizes, int n_in,
                              void* d_out, int out_size) {
    const float* x    = (const float*)d_in[0];
    const float* Wq   = (const float*)d_in[1];
    const float* Wk   = (const float*)d_in[2];
    const float* Wv   = (const float*)d_in[3];
    const float* Wo   = (const float*)d_in[4];
    const float* bo   = (const float*)d_in[5];
    const float* ln1g = (const float*)d_in[6];
    const float* ln1b = (const float*)d_in[7];
    const float* ln2g = (const float*)d_in[8];
    const float* ln2b = (const float*)d_in[9];
    const float* W1   = (const float*)d_in[10];
    const float* b1   = (const float*)d_in[11];
    const float* W2   = (const float*)d_in[12];
    const float* b2   = (const float*)d_in[13];
    float* out = (float*)d_out;

    __half *a, *qkv, *at, *ffh;
    float* x2;
    __half *wqkv, *wo, *w1, *w2;
    cudaGetSymbolAddress((void**)&a,    g_a);
    cudaGetSymbolAddress((void**)&qkv,  g_qkv);
    cudaGetSymbolAddress((void**)&at,   g_at);
    cudaGetSymbolAddress((void**)&ffh,  g_ffh);
    cudaGetSymbolAddress((void**)&x2,   g_x2);
    cudaGetSymbolAddress((void**)&wqkv, g_wqkv);
    cudaGetSymbolAddress((void**)&wo,   g_wo);
    cudaGetSymbolAddress((void**)&w1,   g_w1);
    cudaGetSymbolAddress((void**)&w2,   g_w2);

    cudaFuncSetAttribute(gemm_mma<0, 0>, cudaFuncAttributeMaxDynamicSharedMemorySize, GEMM_SMEM);
    cudaFuncSetAttribute(gemm_mma<0, 1>, cudaFuncAttributeMaxDynamicSharedMemorySize, GEMM_SMEM);
    cudaFuncSetAttribute(gemm_mma<1, 1>, cudaFuncAttributeMaxDynamicSharedMemorySize, GEMM_SMEM);

    dim3 gQKV(QKV_N / 128, M_ROWS / 128);
    dim3 g1024(C_DIM / 128, M_ROWS / 128);
    dim3 g4096(FF_DIM / 128, M_ROWS / 128);

    // all 6 weight transposes in one launch.
    // Wq scaled by (1/8)*log2(e) so softmax can use raw exp2.
    WJobs jobs;
    jobs.src[0] = Wq; jobs.dst[0] = wqkv;                     jobs.K[0] = C_DIM;  jobs.N[0] = C_DIM;  jobs.scale[0] = 0.125f * 1.44269504089f;
    jobs.src[1] = Wk; jobs.dst[1] = wqkv + C_DIM * C_DIM;     jobs.K[1] = C_DIM;  jobs.N[1] = C_DIM;  jobs.scale[1] = 1.0f;
    jobs.src[2] = Wv; jobs.dst[2] = wqkv + 2 * C_DIM * C_DIM; jobs.K[2] = C_DIM;  jobs.N[2] = C_DIM;  jobs.scale[2] = 1.0f;
    jobs.src[3] = Wo; jobs.dst[3] = wo;                       jobs.K[3] = C_DIM;  jobs.N[3] = C_DIM;  jobs.scale[3] = 1.0f;
    jobs.src[4] = W1; jobs.dst[4] = w1;                       jobs.K[4] = C_DIM;  jobs.N[4] = FF_DIM; jobs.scale[4] = 1.0f;
    jobs.src[5] = W2; jobs.dst[5] = w2;                       jobs.K[5] = FF_DIM; jobs.N[5] = C_DIM;  jobs.scale[5] = 1.0f;
    int acc = 0;
    for (int i = 0; i < 6; i++) {
        jobs.start[i] = acc;
        acc += (jobs.N[i] >> 5) * (jobs.K[i] >> 5);
    }
    jobs.start[6] = acc;
    wtrans_all<<<acc, dim3(32, 8)>>>(jobs);

    // ln1 -> fp16 activations
    ln_half<<<M_ROWS, 256>>>(x, ln1g, ln1b, a);
    // fused QKV projection (fp16 out)
    gemm_mma<0, 1><<<gQKV, 256, GEMM_SMEM>>>(a, wqkv, nullptr, nullptr,
                                             nullptr, qkv, QKV_N, C_DIM);
    // flash attention (fp16 tensor cores, exp2 softmax)
    attn_mma<<<dim3(T_SEQ / 128, H_NUM, B_NUM), 256>>>(qkv, at);
    // Wo projection + bias + residual -> x2 (fp32)
    gemm_mma<0, 0><<<g1024, 256, GEMM_SMEM>>>(at, wo, bo, x,
                                              x2, nullptr, C_DIM, C_DIM);
    // ln2 -> fp16
    ln_half<<<M_ROWS, 256>>>(x2, ln2g, ln2b, a);
    // MLP up + bias + ReLU (fp16 out)
    gemm_mma<1, 1><<<g4096, 256, GEMM_SMEM>>>(a, w1, b1, nullptr,
                                              nullptr, ffh, FF_DIM, C_DIM);
    // MLP down + bias + residual -> out (fp32)
    gemm_mma<0, 0><<<g1024, 256, GEMM_SMEM>>>(ffh, w2, b2, x2,
                                              out, nullptr, C_DIM, FF_DIM);
}